// round 8
// baseline (speedup 1.0000x reference)
#include <cuda_runtime.h>
#include <cuda_fp16.h>
#include <cstdint>

// ---------------- problem constants ----------------
#define B_    4
#define CIN   256
#define H_    56
#define W_    56
#define HW    3136
#define OUT_  256
#define WS_   32
#define K2    49
#define KP    52
#define MPROJ 288
#define PC_   272
#define PH    62
#define PW    64

// attn dynamic smem layout (bytes)
#define ATT_ACT0H  0        // half [400*24] = 19200  (rows pt, stride 24 halves = 48B)
#define ATT_SLOG   19200    // half [400*40] = 32000  (rows pt, stride 40 halves = 80B)
#define ATT_SX2    51200    // float[16*112] = 7168
#define ATT_CW1H   58368    // half [16*16]  = 512    ([o][c])
#define ATT_CW2H   58880    // half [32*16]  = 1024   ([g][o])
#define ATT_SX1    59904    // float[128]    = 512
#define ATT_SCB    60416    // float[32]     = 128
#define ATT_S2S    60544    // float[16]
#define ATT_T2S    60608    // float[16]
#define ATT_SINV   60672    // float[256]    = 1024
#define ATT_SMEM   61696

// ---------------- scratch (device globals) --------------------------------
__device__ float  g_wc[MPROJ * CIN];
__device__ float  g_bc[MPROJ];
__device__ float  g_s1[16], g_t1[16];
__device__ __align__(16) __half g_cw1h[256];   // [o][c] fp16
__device__ __align__(16) __half g_cw2h[512];   // [g][o] fp16
__device__ float  g_proj[B_ * MPROJ * HW];
__device__ float  g_pad[(size_t)B_ * PC_ * PH * PW];
__device__ __half g_w[(size_t)B_ * WS_ * HW * KP];
__device__ float  g_agg[B_ * OUT_ * HW];

__device__ __forceinline__ int refl(int i, int n) {
    if (i < 0) i = -i;
    if (i >= n) i = 2 * n - 2 - i;
    return i;
}

__device__ __forceinline__ void mma16816(float (&d)[4], const unsigned (&a)[4],
                                         const unsigned (&b)[2], const float (&c)[4]) {
    asm volatile(
        "mma.sync.aligned.m16n8k16.row.col.f32.f16.f16.f32 "
        "{%0,%1,%2,%3}, {%4,%5,%6,%7}, {%8,%9}, {%10,%11,%12,%13};\n"
        : "=f"(d[0]), "=f"(d[1]), "=f"(d[2]), "=f"(d[3])
        : "r"(a[0]), "r"(a[1]), "r"(a[2]), "r"(a[3]),
          "r"(b[0]), "r"(b[1]),
          "f"(c[0]), "f"(c[1]), "f"(c[2]), "f"(c[3]));
}

__device__ __forceinline__ void ldmatrix_x4(unsigned (&r)[4], uint32_t addr) {
    asm volatile("ldmatrix.sync.aligned.m8n8.x4.shared.b16 {%0,%1,%2,%3}, [%4];\n"
                 : "=r"(r[0]), "=r"(r[1]), "=r"(r[2]), "=r"(r[3]) : "r"(addr));
}

// ---------------- kernel 0: pack weights + bn1 fold + fp16 weights --------
__global__ void pack_kernel(const float* __restrict__ w1, const float* __restrict__ b1,
                            const float* __restrict__ w2, const float* __restrict__ b2,
                            const float* __restrict__ w3, const float* __restrict__ b3,
                            const float* __restrict__ bn1g, const float* __restrict__ bn1b,
                            const float* __restrict__ bn1m, const float* __restrict__ bn1v,
                            const float* __restrict__ cw1, const float* __restrict__ cw2) {
    int i = blockIdx.x * blockDim.x + threadIdx.x;
    if (i < MPROJ * CIN) {
        int r = i / CIN, c = i % CIN;
        float v;
        if (r < 16)      v = w1[r * CIN + c];
        else if (r < 32) v = w2[(r - 16) * CIN + c];
        else             v = w3[(r - 32) * CIN + c];
        g_wc[i] = v;
    }
    if (i < MPROJ) {
        g_bc[i] = (i < 16) ? b1[i] : ((i < 32) ? b2[i - 16] : b3[i - 32]);
    }
    if (i < 16) {
        float s = bn1g[i] * rsqrtf(bn1v[i] + 1e-5f);
        g_s1[i] = s;
        g_t1[i] = bn1b[i] - s * bn1m[i];
    }
    if (i < 256) g_cw1h[i] = __float2half(cw1[i]);    // keep [o][c]
    if (i < 512) g_cw2h[i] = __float2half(cw2[i]);    // keep [g][o]
}

// ---------------- kernel 1: projection GEMM (single-buffered) -------------
#define BM 96
#define BN 64
#define BK 16
__global__ __launch_bounds__(256) void proj_gemm(const float* __restrict__ x) {
    __shared__ float As[BK][BM + 1];
    __shared__ __align__(16) float Bs[BK][BN];

    int b  = blockIdx.z;
    int m0 = blockIdx.y * BM;
    int n0 = blockIdx.x * BN;
    int t  = threadIdx.x;
    int tx = t & 15;
    int ty = t >> 4;

    const float* xb = x + (size_t)b * CIN * HW;

    float acc[6][4];
#pragma unroll
    for (int i = 0; i < 6; i++)
#pragma unroll
        for (int j = 0; j < 4; j++) acc[i][j] = 0.0f;

    for (int k0 = 0; k0 < CIN; k0 += BK) {
#pragma unroll
        for (int q = 0; q < 6; q++) {
            int idx = t + q * 256;
            int col = idx & 15;
            int row = idx >> 4;
            As[col][row] = g_wc[(m0 + row) * CIN + k0 + col];
        }
        {
            int row = t >> 4, cg = t & 15;
            float4 v = *reinterpret_cast<const float4*>(&xb[(size_t)(k0 + row) * HW + n0 + cg * 4]);
            *reinterpret_cast<float4*>(&Bs[row][cg * 4]) = v;
        }
        __syncthreads();
#pragma unroll
        for (int k = 0; k < BK; k++) {
            float a[6];
#pragma unroll
            for (int i = 0; i < 6; i++) a[i] = As[k][ty * 6 + i];
            float4 bv = *reinterpret_cast<float4*>(&Bs[k][tx * 4]);
            float bb[4] = {bv.x, bv.y, bv.z, bv.w};
#pragma unroll
            for (int i = 0; i < 6; i++)
#pragma unroll
                for (int j = 0; j < 4; j++) acc[i][j] = fmaf(a[i], bb[j], acc[i][j]);
        }
        __syncthreads();
    }
#pragma unroll
    for (int i = 0; i < 6; i++) {
        int m = m0 + ty * 6 + i;
        float bias = g_bc[m];
        float vv[4];
#pragma unroll
        for (int j = 0; j < 4; j++) vv[j] = acc[i][j] + bias;
        if (m < 16) {
            float s = g_s1[m], tt = g_t1[m];
#pragma unroll
            for (int j = 0; j < 4; j++) vv[j] = fmaf(s, vv[j], tt);
        } else if (m < 32) {
            float s = g_s1[m - 16];
#pragma unroll
            for (int j = 0; j < 4; j++) vv[j] *= s;
        }
        float4 v = make_float4(vv[0], vv[1], vv[2], vv[3]);
        *reinterpret_cast<float4*>(&g_proj[((size_t)b * MPROJ + m) * HW + n0 + tx * 4]) = v;
    }
}

// ---------------- kernel 1b: reflect-pad channels 16..287 -----------------
__global__ void pad_kernel() {
    int idx = blockIdx.x * 256 + threadIdx.x;
    const int total = B_ * PC_ * PH * PW;
    if (idx >= total) return;
    int col = idx & 63;
    int rest = idx >> 6;
    int r = rest % PH;
    int cb = rest / PH;
    int c = cb % PC_;
    int b = cb / PC_;
    int oy = refl(r - 3, H_), ox = refl(col - 3, W_);
    g_pad[idx] = g_proj[((size_t)(b * MPROJ + 16 + c)) * HW + oy * W_ + ox];
}

// ---------------- kernel 2: attention weights + softmax (HMMA) ------------
// 8 pixels/block, 384 threads = 12 warps. Rows pt = k*8 + pix (tap-major).
__global__ __launch_bounds__(384, 3) void attn_kernel(
    const float* __restrict__ bn2g, const float* __restrict__ bn2b,
    const float* __restrict__ bn2m, const float* __restrict__ bn2v,
    const float* __restrict__ cb) {

    extern __shared__ __align__(16) char smem_raw[];
    __half* act0h = (__half*)(smem_raw + ATT_ACT0H);  // [400][24] (16 used)
    __half* slog  = (__half*)(smem_raw + ATT_SLOG);   // [400][40] (32 used)
    float*  sx2   = (float*)(smem_raw + ATT_SX2);     // [16][112]
    __half* scw1h = (__half*)(smem_raw + ATT_CW1H);   // [o][c]
    __half* scw2h = (__half*)(smem_raw + ATT_CW2H);   // [g][o]
    float*  sx1   = (float*)(smem_raw + ATT_SX1);     // [pix*16+c]
    float*  scb   = (float*)(smem_raw + ATT_SCB);
    float*  s2s   = (float*)(smem_raw + ATT_S2S);
    float*  t2s   = (float*)(smem_raw + ATT_T2S);
    float*  sinv  = (float*)(smem_raw + ATT_SINV);    // [256]

    int t = threadIdx.x;
    int b = blockIdx.y;
    int p0 = blockIdx.x * 8;
    int h = p0 / W_, w0 = p0 % W_;

    // -------- staging --------
    if (t < 32) {
        reinterpret_cast<uint4*>(scw1h)[t] = reinterpret_cast<const uint4*>(g_cw1h)[t];
    } else if (t < 96) {
        reinterpret_cast<uint4*>(scw2h)[t - 32] = reinterpret_cast<const uint4*>(g_cw2h)[t - 32];
    } else if (t < 128) {
        scb[t - 96] = cb[t - 96];
    } else if (t < 144) {
        int c = t - 128;
        float ss = bn2g[c] * rsqrtf(bn2v[c] + 1e-5f);
        s2s[c] = ss; t2s[c] = bn2b[c] - ss * bn2m[c];
    } else if (t < 272) {
        int idx = t - 144;
        int c = idx >> 3, pix = idx & 7;
        sx1[pix * 16 + c] = g_proj[((size_t)b * MPROJ + c) * HW + p0 + pix];
    }
    const float* padb = g_pad + (size_t)b * PC_ * PH * PW;
    for (int i = t; i < 448; i += 384) {
        int c = i / 28, rem = i - c * 28, dy = rem >> 2, cg = rem & 3;
        float4 v = *reinterpret_cast<const float4*>(
            padb + ((size_t)c * PH + h + dy) * PW + w0 + cg * 4);
        *reinterpret_cast<float4*>(sx2 + c * 112 + dy * 16 + cg * 4) = v;
    }
    __syncthreads();

    // -------- phase1: act = relu(x1' - x2') -> fp16, rows pt = k*8+pix ----
    for (int pt = t; pt < 392; pt += 384) {
        int pix = pt & 7, k = pt >> 3;
        int dy = k / 7, dx = k - dy * 7;
        const float* x2p = sx2 + dy * 16 + dx + pix;
        const float* x1p = sx1 + pix * 16;
        __half2* dst = reinterpret_cast<__half2*>(act0h + pt * 24);
#pragma unroll
        for (int q = 0; q < 8; q++) {
            float a0 = fmaxf(x1p[2 * q]     - x2p[(2 * q) * 112],     0.0f);
            float a1 = fmaxf(x1p[2 * q + 1] - x2p[(2 * q + 1) * 112], 0.0f);
            dst[q] = __floats2half2_rn(a0, a1);
        }
    }
    __syncthreads();

    // -------- phase2+3: HMMA GEMM1 (16x16) -> BN2+ReLU -> GEMM2 (16x32) ---
    {
        int warp = t >> 5, lane = t & 31;
        int qp = lane & 3, rp = lane >> 2;
        int k0 = qp * 2;

        // B fragments (hoisted): GEMM1 j=0,1 (o = j*8+rp), GEMM2 j=0..3 (g = j*8+rp)
        unsigned b1f[2][2], b2f[4][2];
#pragma unroll
        for (int j = 0; j < 2; j++) {
            int o = j * 8 + rp;
            b1f[j][0] = *reinterpret_cast<const unsigned*>(scw1h + o * 16 + k0);
            b1f[j][1] = *reinterpret_cast<const unsigned*>(scw1h + o * 16 + k0 + 8);
        }
#pragma unroll
        for (int j = 0; j < 4; j++) {
            int g = j * 8 + rp;
            b2f[j][0] = *reinterpret_cast<const unsigned*>(scw2h + g * 16 + k0);
            b2f[j][1] = *reinterpret_cast<const unsigned*>(scw2h + g * 16 + k0 + 8);
        }
        float s2v[4] = {s2s[k0], s2s[k0 + 1], s2s[k0 + 8], s2s[k0 + 9]};
        float t2v[4] = {t2s[k0], t2s[k0 + 1], t2s[k0 + 8], t2s[k0 + 9]};
        float cbv[4][2];
#pragma unroll
        for (int j = 0; j < 4; j++) {
            cbv[j][0] = scb[j * 8 + k0];
            cbv[j][1] = scb[j * 8 + k0 + 1];
        }

        uint32_t act_base = (uint32_t)__cvta_generic_to_shared(act0h);
        for (int tile = warp; tile < 25; tile += 12) {
            unsigned a1[4];
            uint32_t addr = act_base + (uint32_t)(tile * 16 + (lane & 15)) * 48u
                          + (uint32_t)(lane >> 4) * 16u;
            ldmatrix_x4(a1, addr);

            float z4[4] = {0.f, 0.f, 0.f, 0.f};
            float d0[4], d1[4];
            mma16816(d0, a1, b1f[0], z4);
            mma16816(d1, a1, b1f[1], z4);

            unsigned a2[4];
            {
                __half2 hv;
                hv = __floats2half2_rn(fmaxf(fmaf(s2v[0], d0[0], t2v[0]), 0.f),
                                       fmaxf(fmaf(s2v[1], d0[1], t2v[1]), 0.f));
                a2[0] = *reinterpret_cast<unsigned*>(&hv);
                hv = __floats2half2_rn(fmaxf(fmaf(s2v[0], d0[2], t2v[0]), 0.f),
                                       fmaxf(fmaf(s2v[1], d0[3], t2v[1]), 0.f));
                a2[1] = *reinterpret_cast<unsigned*>(&hv);
                hv = __floats2half2_rn(fmaxf(fmaf(s2v[2], d1[0], t2v[2]), 0.f),
                                       fmaxf(fmaf(s2v[3], d1[1], t2v[3]), 0.f));
                a2[2] = *reinterpret_cast<unsigned*>(&hv);
                hv = __floats2half2_rn(fmaxf(fmaf(s2v[2], d1[2], t2v[2]), 0.f),
                                       fmaxf(fmaf(s2v[3], d1[3], t2v[3]), 0.f));
                a2[3] = *reinterpret_cast<unsigned*>(&hv);
            }

            int r0 = tile * 16 + rp;
            bool lo_ok = (r0 < 392);            // always true (tile<=24 -> r0<=391)
            bool hi_ok = (r0 + 8 < 392);        // false only for tile 24
#pragma unroll
            for (int j = 0; j < 4; j++) {
                float c2[4] = {cbv[j][0], cbv[j][1], cbv[j][0], cbv[j][1]};
                mma16816(c2, a2, b2f[j], c2);
                int g0 = j * 8 + k0;
                if (lo_ok)
                    *reinterpret_cast<__half2*>(slog + r0 * 40 + g0) =
                        __floats2half2_rn(c2[0], c2[1]);
                if (hi_ok)
                    *reinterpret_cast<__half2*>(slog + (r0 + 8) * 40 + g0) =
                        __floats2half2_rn(c2[2], c2[3]);
            }
        }
    }
    __syncthreads();

    // -------- phase4: softmax over 49 taps (exp in place, keep 1/sum) -----
    if (t < 256) {
        int pix = t >> 5, g = t & 31;
        __half* base = slog + pix * 40 + g;
        float m = -1e30f;
#pragma unroll
        for (int k = 0; k < 49; k++) m = fmaxf(m, __half2float(base[k * 320]));
        float s = 0.0f;
#pragma unroll
        for (int k = 0; k < 49; k++) {
            float e = __expf(__half2float(base[k * 320]) - m);
            base[k * 320] = __float2half(e);
            s += e;
        }
        sinv[t] = 1.0f / s;
    }
    __syncthreads();

    // -------- phase5: scale + write fp16 g_w --------
    {
        __half2* gw2 = reinterpret_cast<__half2*>(g_w);
        int r = t / 26, k2 = t - r * 26;
        for (int i = t; i < 6656; i += 384) {
            int pix = r >> 5, g = r & 31;
            float inv = sinv[r];
            int k = 2 * k2;
            float v0 = 0.f, v1 = 0.f;
            if (k < 49)     v0 = __half2float(slog[(k * 8 + pix) * 40 + g]) * inv;
            if (k + 1 < 49) v1 = __half2float(slog[((k + 1) * 8 + pix) * 40 + g]) * inv;
            gw2[(((size_t)(b * WS_ + g)) * HW + p0 + pix) * 26 + k2] =
                __floats2half2_rn(v0, v1);
            r += 14; k2 += 20;
            if (k2 >= 26) { k2 -= 26; r++; }
        }
    }
}

// ---------------- kernel 3: aggregation -----------------------------------
__global__ __launch_bounds__(128) void agg_kernel() {
    __shared__ __align__(4) __half swh[64 * KP];
    __shared__ __align__(16) float sx3[8 * 14 * 24];

    int b = blockIdx.z, g = blockIdx.y, tile = blockIdx.x;
    int ty0 = (tile / 7) * 8, tx0 = (tile % 7) * 8;
    int t = threadIdx.x;

    const __half2* gw2 = reinterpret_cast<const __half2*>(g_w);
    size_t wbase = ((size_t)(b * WS_ + g)) * HW;
    for (int i = t; i < 1664; i += 128) {
        int run = i / 208, off = i - run * 208;
        reinterpret_cast<__half2*>(swh)[run * 208 + off] =
            gw2[(wbase + (ty0 + run) * W_ + tx0) * 26 + off];
    }
    const float* padb = g_pad + ((size_t)(b * PC_) + 16 + g * 8) * PH * PW;
    for (int i = t; i < 448; i += 128) {
        int c = i / 56, rem = i - c * 56, r = rem >> 2, cg = rem & 3;
        float4 v = *reinterpret_cast<const float4*>(
            padb + ((size_t)c * PH + ty0 + r) * PW + tx0 + cg * 4);
        *reinterpret_cast<float4*>(sx3 + (c * 14 + r) * 24 + cg * 4) = v;
    }
    __syncthreads();

    int pl = t & 63, sq = t >> 6;
    int pr = pl >> 3, pc = pl & 7;
    const __half2* wp = reinterpret_cast<const __half2*>(swh + pl * KP);
    const float* xb = sx3 + sq * 4 * 336 + pr * 24 + pc;

    float a0 = 0.f, a1 = 0.f, a2 = 0.f, a3 = 0.f;
#pragma unroll
    for (int k2 = 0; k2 < 25; k2++) {
        float2 wf = __half22float2(wp[k2]);
        {
            int k = 2 * k2;
            int xo = (k / 7) * 24 + (k % 7);
            a0 = fmaf(xb[xo],        wf.x, a0);
            a1 = fmaf(xb[336 + xo],  wf.x, a1);
            a2 = fmaf(xb[672 + xo],  wf.x, a2);
            a3 = fmaf(xb[1008 + xo], wf.x, a3);
        }
        if (2 * k2 + 1 < 49) {
            int k = 2 * k2 + 1;
            int xo = (k / 7) * 24 + (k % 7);
            a0 = fmaf(xb[xo],        wf.y, a0);
            a1 = fmaf(xb[336 + xo],  wf.y, a1);
            a2 = fmaf(xb[672 + xo],  wf.y, a2);
            a3 = fmaf(xb[1008 + xo], wf.y, a3);
        }
    }
    int p = (ty0 + pr) * W_ + tx0 + pc;
    float* dst = g_agg + ((size_t)b * OUT_ + g * 8 + sq * 4) * HW + p;
    dst[0] = a0; dst[HW] = a1; dst[2 * HW] = a2; dst[3 * HW] = a3;
}

// ---------------- kernel 4: position2 grouped conv ------------------------
__global__ __launch_bounds__(128) void pos2_kernel(const float* __restrict__ pos2w,
                                                   float* __restrict__ out) {
    __shared__ __align__(16) float sw[64 * KP];
    __shared__ __align__(16) float spw[8 * 60];
    __shared__ float sxv[8 * 64];

    int b = blockIdx.z, g = blockIdx.y, p0 = blockIdx.x * 64;
    int t = threadIdx.x;

    const __half2* gw2 = reinterpret_cast<const __half2*>(g_w);
    size_t base2 = (((size_t)(b * WS_ + g)) * HW + p0) * 26;
    for (int i = t; i < 1664; i += 128) {
        float2 f = __half22float2(gw2[base2 + i]);
        *reinterpret_cast<float2*>(sw + 2 * i) = f;
    }
    for (int i = t; i < 480; i += 128) {
        int o = i / 60, q = i - o * 60;
        spw[i] = (q < 57) ? pos2w[(g * 8 + o) * 57 + q] : 0.0f;
    }
    for (int i = t; i < 512; i += 128) {
        int s = i >> 6, pl = i & 63;
        sxv[i] = g_agg[((size_t)b * OUT_ + s * 32 + g) * HW + p0 + pl];
    }
    __syncthreads();

    int pl = t & 63, oh = t >> 6;
    float acc[4] = {0.f, 0.f, 0.f, 0.f};
#pragma unroll
    for (int s = 0; s < 8; s++) {
        float xv = sxv[s * 64 + pl];
#pragma unroll
        for (int j = 0; j < 4; j++)
            acc[j] = fmaf(xv, spw[(oh * 4 + j) * 60 + s], acc[j]);
    }
    const float4* w4 = reinterpret_cast<const float4*>(sw + pl * KP);
#pragma unroll
    for (int k4 = 0; k4 < 13; k4++) {
        float4 wv = w4[k4];
#pragma unroll
        for (int j = 0; j < 4; j++) {
            float4 pv = *reinterpret_cast<const float4*>(spw + (oh * 4 + j) * 60 + 8 + k4 * 4);
            acc[j] = fmaf(wv.x, pv.x, acc[j]);
            acc[j] = fmaf(wv.y, pv.y, acc[j]);
            acc[j] = fmaf(wv.z, pv.z, acc[j]);
            acc[j] = fmaf(wv.w, pv.w, acc[j]);
        }
    }
#pragma unroll
    for (int j = 0; j < 4; j++)
        out[((size_t)b * OUT_ + g * 8 + oh * 4 + j) * HW + p0 + pl] = acc[j];
}

// ---------------- launch ---------------------------------------------------
extern "C" void kernel_launch(void* const* d_in, const int* in_sizes, int n_in,
                              void* d_out, int out_size) {
    const float* x    = (const float*)d_in[0];
    const float* w1   = (const float*)d_in[1];
    const float* b1   = (const float*)d_in[2];
    const float* w2   = (const float*)d_in[3];
    const float* b2   = (const float*)d_in[4];
    const float* w3   = (const float*)d_in[5];
    const float* b3   = (const float*)d_in[6];
    const float* bn1g = (const float*)d_in[7];
    const float* bn1b = (const float*)d_in[8];
    const float* bn1m = (const float*)d_in[9];
    const float* bn1v = (const float*)d_in[10];
    const float* cw1  = (const float*)d_in[11];
    const float* bn2g = (const float*)d_in[12];
    const float* bn2b = (const float*)d_in[13];
    const float* bn2m = (const float*)d_in[14];
    const float* bn2v = (const float*)d_in[15];
    const float* cw2  = (const float*)d_in[16];
    const float* cb   = (const float*)d_in[17];
    const float* p2w  = (const float*)d_in[18];
    float* out = (float*)d_out;

    cudaFuncSetAttribute(attn_kernel, cudaFuncAttributeMaxDynamicSharedMemorySize, ATT_SMEM);

    pack_kernel<<<(MPROJ * CIN + 255) / 256, 256>>>(w1, b1, w2, b2, w3, b3,
                                                    bn1g, bn1b, bn1m, bn1v, cw1, cw2);

    dim3 gg(HW / BN, MPROJ / BM, B_);
    proj_gemm<<<gg, 256>>>(x);

    const int pad_total = B_ * PC_ * PH * PW;
    pad_kernel<<<(pad_total + 255) / 256, 256>>>();

    attn_kernel<<<dim3(HW / 8, B_), 384, ATT_SMEM>>>(bn2g, bn2b, bn2m, bn2v, cb);

    dim3 ga(49, WS_, B_);
    agg_kernel<<<ga, 128>>>();
    pos2_kernel<<<ga, 128>>>(p2w, out);
}

// round 10
// speedup vs baseline: 1.0851x; 1.0851x over previous
#include <cuda_runtime.h>
#include <cuda_fp16.h>
#include <cstdint>

// ---------------- problem constants ----------------
#define B_    4
#define CIN   256
#define H_    56
#define W_    56
#define HW    3136
#define OUT_  256
#define WS_   32
#define K2    49
#define KP    52
#define MPROJ 288
#define PC_   272
#define PH    62
#define PW    64

// attn dynamic smem layout (bytes) — R7 version
#define ATT_ACT0   0        // float[392*16]  = 25088
#define ATT_SLOG   25088    // half [256*52]  = 26624
#define ATT_SX2    51712    // float[16*112]  = 7168
#define ATT_CW1    58880    // float[256]     = 1024
#define ATT_CW2    59904    // float[512]     = 2048
#define ATT_SX1    61952    // float[128]     = 512
#define ATT_SCB    62464    // float[32]      = 128
#define ATT_S2S    62592    // float[16]      = 64
#define ATT_T2S    62656    // float[16]      = 64
#define ATT_SINV   62720    // float[256]     = 1024
#define ATT_SMEM   63744

// ---------------- scratch (device globals) --------------------------------
__device__ float  g_wc[MPROJ * CIN];
__device__ float  g_bc[MPROJ];
__device__ float  g_s1[16], g_t1[16];
__device__ float  g_cw1t[256];     // [c][o] transposed
__device__ float  g_cw2t[512];     // [o][g] transposed
__device__ float  g_proj[B_ * MPROJ * HW];
__device__ float  g_pad[(size_t)B_ * PC_ * PH * PW];
__device__ __half g_w[(size_t)B_ * WS_ * HW * KP];
__device__ float  g_agg[B_ * OUT_ * HW];

__device__ __forceinline__ int refl(int i, int n) {
    if (i < 0) i = -i;
    if (i >= n) i = 2 * n - 2 - i;
    return i;
}

// FIX: cvt.rna.tf32.f32 requires a .b32 destination -> "=r", reinterpret.
__device__ __forceinline__ float to_tf32(float x) {
    unsigned y;
    asm("cvt.rna.tf32.f32 %0, %1;" : "=r"(y) : "f"(x));
    return __uint_as_float(y);
}

__device__ __forceinline__ void mma_tf32(float (&d)[4], const unsigned (&a)[4],
                                         const unsigned (&b)[2]) {
    asm volatile(
        "mma.sync.aligned.m16n8k8.row.col.f32.tf32.tf32.f32 "
        "{%0,%1,%2,%3}, {%4,%5,%6,%7}, {%8,%9}, {%0,%1,%2,%3};\n"
        : "+f"(d[0]), "+f"(d[1]), "+f"(d[2]), "+f"(d[3])
        : "r"(a[0]), "r"(a[1]), "r"(a[2]), "r"(a[3]),
          "r"(b[0]), "r"(b[1]));
}

// ---------------- kernel 0: pack weights + bn1 fold + transposes ----------
__global__ void pack_kernel(const float* __restrict__ w1, const float* __restrict__ b1,
                            const float* __restrict__ w2, const float* __restrict__ b2,
                            const float* __restrict__ w3, const float* __restrict__ b3,
                            const float* __restrict__ bn1g, const float* __restrict__ bn1b,
                            const float* __restrict__ bn1m, const float* __restrict__ bn1v,
                            const float* __restrict__ cw1, const float* __restrict__ cw2) {
    int i = blockIdx.x * blockDim.x + threadIdx.x;
    if (i < MPROJ * CIN) {
        int r = i / CIN, c = i % CIN;
        float v;
        if (r < 16)      v = w1[r * CIN + c];
        else if (r < 32) v = w2[(r - 16) * CIN + c];
        else             v = w3[(r - 32) * CIN + c];
        g_wc[i] = v;
    }
    if (i < MPROJ) {
        g_bc[i] = (i < 16) ? b1[i] : ((i < 32) ? b2[i - 16] : b3[i - 32]);
    }
    if (i < 16) {
        float s = bn1g[i] * rsqrtf(bn1v[i] + 1e-5f);
        g_s1[i] = s;
        g_t1[i] = bn1b[i] - s * bn1m[i];
    }
    if (i < 256) g_cw1t[i] = cw1[(i & 15) * 16 + (i >> 4)];    // [c][o]
    if (i < 512) g_cw2t[i] = cw2[(i & 31) * 16 + (i >> 5)];    // [o][g]
}

// ---------------- kernel 1: projection GEMM via split-TF32 MMA ------------
// C[b][m][n] = sum_k W[m][k] X[b][k][n]; BM=96, BN=64, BK=16; 256 thr = 8 warps.
// Warp grid 2x4: warp covers 48 m-rows (3 m16 tiles) x 16 n-cols (2 n8 tiles).
// 3xTF32: W,X split big/small; D += Wb*Xb + Wb*Xs + Ws*Xb  (~fp32 accuracy).
#define ASTR 104
#define BSTR 72
__global__ __launch_bounds__(256) void proj_gemm(const float* __restrict__ x) {
    __shared__ float Asb[16][ASTR], Ass[16][ASTR];   // [k][m] big/small
    __shared__ __align__(16) float Bsb[16][BSTR], Bss[16][BSTR];   // [k][n]

    int b  = blockIdx.z;
    int m0 = blockIdx.y * 96;
    int n0 = blockIdx.x * 64;
    int t  = threadIdx.x;
    int warp = t >> 5, lane = t & 31;
    int wm = warp >> 2, wn = warp & 3;
    int r = lane >> 2, q = lane & 3;

    const float* xb = x + (size_t)b * CIN * HW;

    float acc[3][2][4];
#pragma unroll
    for (int i = 0; i < 3; i++)
#pragma unroll
        for (int j = 0; j < 2; j++)
#pragma unroll
            for (int c = 0; c < 4; c++) acc[i][j][c] = 0.0f;

    for (int k0 = 0; k0 < CIN; k0 += 16) {
        // stage A (96x16 -> [k][m]) with big/small split
#pragma unroll
        for (int i = 0; i < 6; i++) {
            int idx = t + i * 256;
            int col = idx & 15, row = idx >> 4;
            float v = g_wc[(m0 + row) * CIN + k0 + col];
            float big = to_tf32(v);
            Asb[col][row] = big;
            Ass[col][row] = to_tf32(v - big);
        }
        // stage B (16x64 -> [k][n])
        {
            int row = t >> 4, cg = t & 15;
            float4 v = *reinterpret_cast<const float4*>(
                &xb[(size_t)(k0 + row) * HW + n0 + cg * 4]);
            float4 bg = make_float4(to_tf32(v.x), to_tf32(v.y), to_tf32(v.z), to_tf32(v.w));
            float4 sm = make_float4(to_tf32(v.x - bg.x), to_tf32(v.y - bg.y),
                                    to_tf32(v.z - bg.z), to_tf32(v.w - bg.w));
            *reinterpret_cast<float4*>(&Bsb[row][cg * 4]) = bg;
            *reinterpret_cast<float4*>(&Bss[row][cg * 4]) = sm;
        }
        __syncthreads();

#pragma unroll
        for (int kk = 0; kk < 16; kk += 8) {
            unsigned ab[3][4], as_[3][4];
#pragma unroll
            for (int i = 0; i < 3; i++) {
                int mb = wm * 48 + i * 16;
                ab[i][0] = __float_as_uint(Asb[kk + q][mb + r]);
                ab[i][1] = __float_as_uint(Asb[kk + q][mb + r + 8]);
                ab[i][2] = __float_as_uint(Asb[kk + q + 4][mb + r]);
                ab[i][3] = __float_as_uint(Asb[kk + q + 4][mb + r + 8]);
                as_[i][0] = __float_as_uint(Ass[kk + q][mb + r]);
                as_[i][1] = __float_as_uint(Ass[kk + q][mb + r + 8]);
                as_[i][2] = __float_as_uint(Ass[kk + q + 4][mb + r]);
                as_[i][3] = __float_as_uint(Ass[kk + q + 4][mb + r + 8]);
            }
            unsigned bb[2][2], bs[2][2];
#pragma unroll
            for (int j = 0; j < 2; j++) {
                int nb = wn * 16 + j * 8;
                bb[j][0] = __float_as_uint(Bsb[kk + q][nb + r]);
                bb[j][1] = __float_as_uint(Bsb[kk + q + 4][nb + r]);
                bs[j][0] = __float_as_uint(Bss[kk + q][nb + r]);
                bs[j][1] = __float_as_uint(Bss[kk + q + 4][nb + r]);
            }
#pragma unroll
            for (int i = 0; i < 3; i++)
#pragma unroll
                for (int j = 0; j < 2; j++) {
                    mma_tf32(acc[i][j], ab[i], bb[j]);
                    mma_tf32(acc[i][j], ab[i], bs[j]);
                    mma_tf32(acc[i][j], as_[i], bb[j]);
                }
        }
        __syncthreads();
    }

    // epilogue: bias + BN1 fold, write fp32
#pragma unroll
    for (int i = 0; i < 3; i++) {
        int mlo = m0 + wm * 48 + i * 16 + r;
        int mhi = mlo + 8;
#pragma unroll
        for (int j = 0; j < 2; j++) {
            int n = n0 + wn * 16 + j * 8 + 2 * q;
            float v0 = acc[i][j][0] + g_bc[mlo];
            float v1 = acc[i][j][1] + g_bc[mlo];
            float v2 = acc[i][j][2] + g_bc[mhi];
            float v3 = acc[i][j][3] + g_bc[mhi];
            if (mlo < 16)      { float s = g_s1[mlo], tt = g_t1[mlo];
                                 v0 = fmaf(s, v0, tt); v1 = fmaf(s, v1, tt); }
            else if (mlo < 32) { float s = g_s1[mlo - 16]; v0 *= s; v1 *= s; }
            if (mhi < 16)      { float s = g_s1[mhi], tt = g_t1[mhi];
                                 v2 = fmaf(s, v2, tt); v3 = fmaf(s, v3, tt); }
            else if (mhi < 32) { float s = g_s1[mhi - 16]; v2 *= s; v3 *= s; }
            *reinterpret_cast<float2*>(&g_proj[((size_t)b * MPROJ + mlo) * HW + n]) =
                make_float2(v0, v1);
            *reinterpret_cast<float2*>(&g_proj[((size_t)b * MPROJ + mhi) * HW + n]) =
                make_float2(v2, v3);
        }
    }
}

// ---------------- kernel 1b: reflect-pad channels 16..287 -----------------
__global__ void pad_kernel() {
    int idx = blockIdx.x * 256 + threadIdx.x;
    const int total = B_ * PC_ * PH * PW;
    if (idx >= total) return;
    int col = idx & 63;
    int rest = idx >> 6;
    int r = rest % PH;
    int cb = rest / PH;
    int c = cb % PC_;
    int b = cb / PC_;
    int oy = refl(r - 3, H_), ox = refl(col - 3, W_);
    g_pad[idx] = g_proj[((size_t)(b * MPROJ + 16 + c)) * HW + oy * W_ + ox];
}

// ---------------- kernel 2: attention weights + softmax (R7 SIMT) ---------
__global__ __launch_bounds__(384, 3) void attn_kernel(
    const float* __restrict__ bn2g, const float* __restrict__ bn2b,
    const float* __restrict__ bn2m, const float* __restrict__ bn2v,
    const float* __restrict__ cb) {

    extern __shared__ __align__(16) char smem_raw[];
    float*  act0  = (float*)(smem_raw + ATT_ACT0);    // [392][16]
    __half* slog  = (__half*)(smem_raw + ATT_SLOG);   // [256][52]
    float*  sx2   = (float*)(smem_raw + ATT_SX2);     // [16][112]
    float*  scw1t = (float*)(smem_raw + ATT_CW1);     // [c][o]
    float*  scw2t = (float*)(smem_raw + ATT_CW2);     // [o][g]
    float*  sx1   = (float*)(smem_raw + ATT_SX1);     // [pix*16+c]
    float*  scb   = (float*)(smem_raw + ATT_SCB);
    float*  s2s   = (float*)(smem_raw + ATT_S2S);
    float*  t2s   = (float*)(smem_raw + ATT_T2S);
    float*  sinv  = (float*)(smem_raw + ATT_SINV);    // [256]

    int t = threadIdx.x;
    int b = blockIdx.y;
    int p0 = blockIdx.x * 8;
    int h = p0 / W_, w0 = p0 % W_;

    if (t < 64)
        reinterpret_cast<float4*>(scw1t)[t] = reinterpret_cast<const float4*>(g_cw1t)[t];
    else if (t < 192)
        reinterpret_cast<float4*>(scw2t)[t - 64] = reinterpret_cast<const float4*>(g_cw2t)[t - 64];
    else if (t < 224) {
        scb[t - 192] = cb[t - 192];
    } else if (t < 240) {
        int c = t - 224;
        float ss = bn2g[c] * rsqrtf(bn2v[c] + 1e-5f);
        s2s[c] = ss; t2s[c] = bn2b[c] - ss * bn2m[c];
    } else if (t < 368) {
        int idx = t - 240;
        int c = idx >> 3, pix = idx & 7;
        sx1[pix * 16 + c] = g_proj[((size_t)b * MPROJ + c) * HW + p0 + pix];
    }
    const float* padb = g_pad + (size_t)b * PC_ * PH * PW;
    for (int i = t; i < 448; i += 384) {
        int c = i / 28, rem = i - c * 28, dy = rem >> 2, cg = rem & 3;
        float4 v = *reinterpret_cast<const float4*>(
            padb + ((size_t)c * PH + h + dy) * PW + w0 + cg * 4);
        *reinterpret_cast<float4*>(sx2 + c * 112 + dy * 16 + cg * 4) = v;
    }
    __syncthreads();

    for (int pt = t; pt < 392; pt += 384) {
        int pix = pt / 49, k = pt - pix * 49;
        int dy = k / 7, dx = k - dy * 7;
        const float* x2p = sx2 + dy * 16 + dx + pix;
        const float* x1p = sx1 + pix * 16;
        float av[16];
#pragma unroll
        for (int c = 0; c < 16; c++) av[c] = fmaxf(x1p[c] - x2p[c * 112], 0.0f);
        float4* dst = reinterpret_cast<float4*>(act0 + pt * 16);
#pragma unroll
        for (int q = 0; q < 4; q++)
            dst[q] = make_float4(av[q * 4], av[q * 4 + 1], av[q * 4 + 2], av[q * 4 + 3]);
    }
    __syncthreads();

    {
        int op = t & 7, pb = t >> 3;
        int o0 = op * 2;
        float2 w1r[16];
#pragma unroll
        for (int c = 0; c < 16; c++)
            w1r[c] = *reinterpret_cast<const float2*>(scw1t + c * 16 + o0);
        float s2a = s2s[o0], s2b = s2s[o0 + 1];
        float t2a = t2s[o0], t2b = t2s[o0 + 1];
        for (int pt = pb; pt < 392; pt += 48) {
            const float4* ap = reinterpret_cast<const float4*>(act0 + pt * 16);
            float a[16];
            *reinterpret_cast<float4*>(a + 0)  = ap[0];
            *reinterpret_cast<float4*>(a + 4)  = ap[1];
            *reinterpret_cast<float4*>(a + 8)  = ap[2];
            *reinterpret_cast<float4*>(a + 12) = ap[3];
            float h0 = 0.0f, h1 = 0.0f;
#pragma unroll
            for (int c = 0; c < 16; c++) {
                h0 = fmaf(a[c], w1r[c].x, h0);
                h1 = fmaf(a[c], w1r[c].y, h1);
            }
            __syncwarp();
            float r0 = fmaxf(fmaf(s2a, h0, t2a), 0.0f);
            float r1 = fmaxf(fmaf(s2b, h1, t2b), 0.0f);
            *reinterpret_cast<float2*>(act0 + pt * 16 + o0) = make_float2(r0, r1);
            __syncwarp();
        }
    }
    __syncthreads();

    {
        int gp = t & 15, pb = t >> 4;
        int g0 = gp * 2;
        float2 w2r[16];
#pragma unroll
        for (int o = 0; o < 16; o++)
            w2r[o] = *reinterpret_cast<const float2*>(scw2t + o * 32 + g0);
        float bias0 = scb[g0], bias1 = scb[g0 + 1];
        int pix = 0, k = pb;
        for (int pt = pb; pt < 392; pt += 24) {
            const float4* ap = reinterpret_cast<const float4*>(act0 + pt * 16);
            float a[16];
            *reinterpret_cast<float4*>(a + 0)  = ap[0];
            *reinterpret_cast<float4*>(a + 4)  = ap[1];
            *reinterpret_cast<float4*>(a + 8)  = ap[2];
            *reinterpret_cast<float4*>(a + 12) = ap[3];
            float h0 = bias0, h1 = bias1;
#pragma unroll
            for (int o = 0; o < 16; o++) {
                h0 = fmaf(a[o], w2r[o].x, h0);
                h1 = fmaf(a[o], w2r[o].y, h1);
            }
            int rowb = (pix * 32 + g0) * 52 + k;
            slog[rowb]      = __float2half(h0);
            slog[rowb + 52] = __float2half(h1);
            k += 24;
            if (k >= 49) { k -= 49; pix++; }
        }
    }
    __syncthreads();

    if (t < 256) {
        __half2* row = reinterpret_cast<__half2*>(slog) + t * 26;
        float m = -1e30f;
#pragma unroll
        for (int k2 = 0; k2 < 24; k2++) {
            float2 f = __half22float2(row[k2]);
            m = fmaxf(m, fmaxf(f.x, f.y));
        }
        m = fmaxf(m, __half22float2(row[24]).x);
        float s = 0.0f;
#pragma unroll
        for (int k2 = 0; k2 < 24; k2++) {
            float2 f = __half22float2(row[k2]);
            float ex = __expf(f.x - m), ey = __expf(f.y - m);
            s += ex + ey;
            row[k2] = __floats2half2_rn(ex, ey);
        }
        {
            float ex = __expf(__half22float2(row[24]).x - m);
            s += ex;
            row[24] = __floats2half2_rn(ex, 0.0f);
            row[25] = __floats2half2_rn(0.0f, 0.0f);
        }
        sinv[t] = 1.0f / s;
    }
    __syncthreads();

    {
        __half2* gw2 = reinterpret_cast<__half2*>(g_w);
        const __half2* sl2 = reinterpret_cast<const __half2*>(slog);
        int r = t / 26, k2 = t - r * 26;
        for (int i = t; i < 6656; i += 384) {
            int pix = r >> 5, g = r & 31;
            float2 f = __half22float2(sl2[r * 26 + k2]);
            float inv = sinv[r];
            gw2[(((size_t)(b * WS_ + g)) * HW + p0 + pix) * 26 + k2] =
                __floats2half2_rn(f.x * inv, f.y * inv);
            r += 14; k2 += 20;
            if (k2 >= 26) { k2 -= 26; r++; }
        }
    }
}

// ---------------- kernel 3: aggregation -----------------------------------
__global__ __launch_bounds__(128) void agg_kernel() {
    __shared__ __align__(4) __half swh[64 * KP];
    __shared__ __align__(16) float sx3[8 * 14 * 24];

    int b = blockIdx.z, g = blockIdx.y, tile = blockIdx.x;
    int ty0 = (tile / 7) * 8, tx0 = (tile % 7) * 8;
    int t = threadIdx.x;

    const __half2* gw2 = reinterpret_cast<const __half2*>(g_w);
    size_t wbase = ((size_t)(b * WS_ + g)) * HW;
    for (int i = t; i < 1664; i += 128) {
        int run = i / 208, off = i - run * 208;
        reinterpret_cast<__half2*>(swh)[run * 208 + off] =
            gw2[(wbase + (ty0 + run) * W_ + tx0) * 26 + off];
    }
    const float* padb = g_pad + ((size_t)(b * PC_) + 16 + g * 8) * PH * PW;
    for (int i = t; i < 448; i += 128) {
        int c = i / 56, rem = i - c * 56, r = rem >> 2, cg = rem & 3;
        float4 v = *reinterpret_cast<const float4*>(
            padb + ((size_t)c * PH + ty0 + r) * PW + tx0 + cg * 4);
        *reinterpret_cast<float4*>(sx3 + (c * 14 + r) * 24 + cg * 4) = v;
    }
    __syncthreads();

    int pl = t & 63, sq = t >> 6;
    int pr = pl >> 3, pc = pl & 7;
    const __half2* wp = reinterpret_cast<const __half2*>(swh + pl * KP);
    const float* xb = sx3 + sq * 4 * 336 + pr * 24 + pc;

    float a0 = 0.f, a1 = 0.f, a2 = 0.f, a3 = 0.f;
#pragma unroll
    for (int k2 = 0; k2 < 25; k2++) {
        float2 wf = __half22float2(wp[k2]);
        {
            int k = 2 * k2;
            int xo = (k / 7) * 24 + (k % 7);
            a0 = fmaf(xb[xo],        wf.x, a0);
            a1 = fmaf(xb[336 + xo],  wf.x, a1);
            a2 = fmaf(xb[672 + xo],  wf.x, a2);
            a3 = fmaf(xb[1008 + xo], wf.x, a3);
        }
        if (2 * k2 + 1 < 49) {
            int k = 2 * k2 + 1;
            int xo = (k / 7) * 24 + (k % 7);
            a0 = fmaf(xb[xo],        wf.y, a0);
            a1 = fmaf(xb[336 + xo],  wf.y, a1);
            a2 = fmaf(xb[672 + xo],  wf.y, a2);
            a3 = fmaf(xb[1008 + xo], wf.y, a3);
        }
    }
    int p = (ty0 + pr) * W_ + tx0 + pc;
    float* dst = g_agg + ((size_t)b * OUT_ + g * 8 + sq * 4) * HW + p;
    dst[0] = a0; dst[HW] = a1; dst[2 * HW] = a2; dst[3 * HW] = a3;
}

// ---------------- kernel 4: position2 grouped conv ------------------------
__global__ __launch_bounds__(128) void pos2_kernel(const float* __restrict__ pos2w,
                                                   float* __restrict__ out) {
    __shared__ __align__(16) float sw[64 * KP];
    __shared__ __align__(16) float spw[8 * 60];
    __shared__ float sxv[8 * 64];

    int b = blockIdx.z, g = blockIdx.y, p0 = blockIdx.x * 64;
    int t = threadIdx.x;

    const __half2* gw2 = reinterpret_cast<const __half2*>(g_w);
    size_t base2 = (((size_t)(b * WS_ + g)) * HW + p0) * 26;
    for (int i = t; i < 1664; i += 128) {
        float2 f = __half22float2(gw2[base2 + i]);
        *reinterpret_cast<float2*>(sw + 2 * i) = f;
    }
    for (int i = t; i < 480; i += 128) {
        int o = i / 60, q = i - o * 60;
        spw[i] = (q < 57) ? pos2w[(g * 8 + o) * 57 + q] : 0.0f;
    }
    for (int i = t; i < 512; i += 128) {
        int s = i >> 6, pl = i & 63;
        sxv[i] = g_agg[((size_t)b * OUT_ + s * 32 + g) * HW + p0 + pl];
    }
    __syncthreads();

    int pl = t & 63, oh = t >> 6;
    float acc[4] = {0.f, 0.f, 0.f, 0.f};
#pragma unroll
    for (int s = 0; s < 8; s++) {
        float xv = sxv[s * 64 + pl];
#pragma unroll
        for (int j = 0; j < 4; j++)
            acc[j] = fmaf(xv, spw[(oh * 4 + j) * 60 + s], acc[j]);
    }
    const float4* w4 = reinterpret_cast<const float4*>(sw + pl * KP);
#pragma unroll
    for (int k4 = 0; k4 < 13; k4++) {
        float4 wv = w4[k4];
#pragma unroll
        for (int j = 0; j < 4; j++) {
            float4 pv = *reinterpret_cast<const float4*>(spw + (oh * 4 + j) * 60 + 8 + k4 * 4);
            acc[j] = fmaf(wv.x, pv.x, acc[j]);
            acc[j] = fmaf(wv.y, pv.y, acc[j]);
            acc[j] = fmaf(wv.z, pv.z, acc[j]);
            acc[j] = fmaf(wv.w, pv.w, acc[j]);
        }
    }
#pragma unroll
    for (int j = 0; j < 4; j++)
        out[((size_t)b * OUT_ + g * 8 + oh * 4 + j) * HW + p0 + pl] = acc[j];
}

// ---------------- launch ---------------------------------------------------
extern "C" void kernel_launch(void* const* d_in, const int* in_sizes, int n_in,
                              void* d_out, int out_size) {
    const float* x    = (const float*)d_in[0];
    const float* w1   = (const float*)d_in[1];
    const float* b1   = (const float*)d_in[2];
    const float* w2   = (const float*)d_in[3];
    const float* b2   = (const float*)d_in[4];
    const float* w3   = (const float*)d_in[5];
    const float* b3   = (const float*)d_in[6];
    const float* bn1g = (const float*)d_in[7];
    const float* bn1b = (const float*)d_in[8];
    const float* bn1m = (const float*)d_in[9];
    const float* bn1v = (const float*)d_in[10];
    const float* cw1  = (const float*)d_in[11];
    const float* bn2g = (const float*)d_in[12];
    const float* bn2b = (const float*)d_in[13];
    const float* bn2m = (const float*)d_in[14];
    const float* bn2v = (const float*)d_in[15];
    const float* cw2  = (const float*)d_in[16];
    const float* cb   = (const float*)d_in[17];
    const float* p2w  = (const float*)d_in[18];
    float* out = (float*)d_out;

    cudaFuncSetAttribute(attn_kernel, cudaFuncAttributeMaxDynamicSharedMemorySize, ATT_SMEM);

    pack_kernel<<<(MPROJ * CIN + 255) / 256, 256>>>(w1, b1, w2, b2, w3, b3,
                                                    bn1g, bn1b, bn1m, bn1v, cw1, cw2);

    dim3 gg(HW / 64, MPROJ / 96, B_);   // 49 x 3 x 4
    proj_gemm<<<gg, 256>>>(x);

    const int pad_total = B_ * PC_ * PH * PW;
    pad_kernel<<<(pad_total + 255) / 256, 256>>>();

    attn_kernel<<<dim3(HW / 8, B_), 384, ATT_SMEM>>>(bn2g, bn2b, bn2m, bn2v, cb);

    dim3 ga(49, WS_, B_);
    agg_kernel<<<ga, 128>>>();
    pos2_kernel<<<ga, 128>>>(p2w, out);
}

// round 11
// speedup vs baseline: 1.2403x; 1.1431x over previous
#include <cuda_runtime.h>
#include <cuda_fp16.h>
#include <cstdint>

// ---------------- problem constants ----------------
#define B_    4
#define CIN   256
#define H_    56
#define W_    56
#define HW    3136
#define OUT_  256
#define WS_   32
#define K2    49
#define KP    52
#define MPROJ 288
#define PC_   272
#define PH    62
#define PW    64

// attn dynamic smem layout (bytes)
// union region: act0h (half[400][24], 19200B, phases 1-3) / slog2 (half[256][52], 26624B, phases 4-5)
#define ATT_U0     0
#define ATT_SLOG   26624    // half [400][40] = 32000 (HMMA logits, row stride 80B)
#define ATT_SX2    58624    // float[16*112]  = 7168
#define ATT_CW1H   65792    // half [16][16]  = 512   ([o][c])
#define ATT_CW2H   66304    // half [32][16]  = 1024  ([g][o])
#define ATT_SX1    67328    // float[128]     = 512
#define ATT_SCB    67840    // float[32]      = 128
#define ATT_S2S    67968    // float[16]      = 64
#define ATT_T2S    68032    // float[16]      = 64
#define ATT_SINV   68096    // float[256]     = 1024
#define ATT_SMEM   69120

// ---------------- scratch (device globals) --------------------------------
__device__ float  g_wc[MPROJ * CIN];
__device__ float  g_bc[MPROJ];
__device__ float  g_s1[16], g_t1[16];
__device__ __align__(16) __half g_cw1h[256];   // [o][c] fp16
__device__ __align__(16) __half g_cw2h[512];   // [g][o] fp16
__device__ float  g_proj[B_ * MPROJ * HW];
__device__ float  g_pad[(size_t)B_ * PC_ * PH * PW];
__device__ __half g_w[(size_t)B_ * WS_ * HW * KP];
__device__ float  g_agg[B_ * OUT_ * HW];

__device__ __forceinline__ int refl(int i, int n) {
    if (i < 0) i = -i;
    if (i >= n) i = 2 * n - 2 - i;
    return i;
}

__device__ __forceinline__ void mma16816(float (&d)[4], const unsigned (&a)[4],
                                         const unsigned (&b)[2], const float (&c)[4]) {
    asm volatile(
        "mma.sync.aligned.m16n8k16.row.col.f32.f16.f16.f32 "
        "{%0,%1,%2,%3}, {%4,%5,%6,%7}, {%8,%9}, {%10,%11,%12,%13};\n"
        : "=f"(d[0]), "=f"(d[1]), "=f"(d[2]), "=f"(d[3])
        : "r"(a[0]), "r"(a[1]), "r"(a[2]), "r"(a[3]),
          "r"(b[0]), "r"(b[1]),
          "f"(c[0]), "f"(c[1]), "f"(c[2]), "f"(c[3]));
}

__device__ __forceinline__ void ldmatrix_x4(unsigned (&r)[4], uint32_t addr) {
    asm volatile("ldmatrix.sync.aligned.m8n8.x4.shared.b16 {%0,%1,%2,%3}, [%4];\n"
                 : "=r"(r[0]), "=r"(r[1]), "=r"(r[2]), "=r"(r[3]) : "r"(addr));
}

// ---------------- kernel 0: pack weights + bn1 fold + fp16 weights --------
__global__ void pack_kernel(const float* __restrict__ w1, const float* __restrict__ b1,
                            const float* __restrict__ w2, const float* __restrict__ b2,
                            const float* __restrict__ w3, const float* __restrict__ b3,
                            const float* __restrict__ bn1g, const float* __restrict__ bn1b,
                            const float* __restrict__ bn1m, const float* __restrict__ bn1v,
                            const float* __restrict__ cw1, const float* __restrict__ cw2) {
    int i = blockIdx.x * blockDim.x + threadIdx.x;
    if (i < MPROJ * CIN) {
        int r = i / CIN, c = i % CIN;
        float v;
        if (r < 16)      v = w1[r * CIN + c];
        else if (r < 32) v = w2[(r - 16) * CIN + c];
        else             v = w3[(r - 32) * CIN + c];
        g_wc[i] = v;
    }
    if (i < MPROJ) {
        g_bc[i] = (i < 16) ? b1[i] : ((i < 32) ? b2[i - 16] : b3[i - 32]);
    }
    if (i < 16) {
        float s = bn1g[i] * rsqrtf(bn1v[i] + 1e-5f);
        g_s1[i] = s;
        g_t1[i] = bn1b[i] - s * bn1m[i];
    }
    if (i < 256) g_cw1h[i] = __float2half(cw1[i]);    // [o][c]
    if (i < 512) g_cw2h[i] = __float2half(cw2[i]);    // [g][o]
}

// ---------------- kernel 1: projection GEMM (single-buffered SIMT) --------
#define BM 96
#define BN 64
#define BK 16
__global__ __launch_bounds__(256) void proj_gemm(const float* __restrict__ x) {
    __shared__ float As[BK][BM + 1];
    __shared__ __align__(16) float Bs[BK][BN];

    int b  = blockIdx.z;
    int m0 = blockIdx.y * BM;
    int n0 = blockIdx.x * BN;
    int t  = threadIdx.x;
    int tx = t & 15;
    int ty = t >> 4;

    const float* xb = x + (size_t)b * CIN * HW;

    float acc[6][4];
#pragma unroll
    for (int i = 0; i < 6; i++)
#pragma unroll
        for (int j = 0; j < 4; j++) acc[i][j] = 0.0f;

    for (int k0 = 0; k0 < CIN; k0 += BK) {
#pragma unroll
        for (int q = 0; q < 6; q++) {
            int idx = t + q * 256;
            int col = idx & 15;
            int row = idx >> 4;
            As[col][row] = g_wc[(m0 + row) * CIN + k0 + col];
        }
        {
            int row = t >> 4, cg = t & 15;
            float4 v = *reinterpret_cast<const float4*>(&xb[(size_t)(k0 + row) * HW + n0 + cg * 4]);
            *reinterpret_cast<float4*>(&Bs[row][cg * 4]) = v;
        }
        __syncthreads();
#pragma unroll
        for (int k = 0; k < BK; k++) {
            float a[6];
#pragma unroll
            for (int i = 0; i < 6; i++) a[i] = As[k][ty * 6 + i];
            float4 bv = *reinterpret_cast<float4*>(&Bs[k][tx * 4]);
            float bb[4] = {bv.x, bv.y, bv.z, bv.w};
#pragma unroll
            for (int i = 0; i < 6; i++)
#pragma unroll
                for (int j = 0; j < 4; j++) acc[i][j] = fmaf(a[i], bb[j], acc[i][j]);
        }
        __syncthreads();
    }
#pragma unroll
    for (int i = 0; i < 6; i++) {
        int m = m0 + ty * 6 + i;
        float bias = g_bc[m];
        float vv[4];
#pragma unroll
        for (int j = 0; j < 4; j++) vv[j] = acc[i][j] + bias;
        if (m < 16) {
            float s = g_s1[m], tt = g_t1[m];
#pragma unroll
            for (int j = 0; j < 4; j++) vv[j] = fmaf(s, vv[j], tt);
        } else if (m < 32) {
            float s = g_s1[m - 16];
#pragma unroll
            for (int j = 0; j < 4; j++) vv[j] *= s;
        }
        float4 v = make_float4(vv[0], vv[1], vv[2], vv[3]);
        *reinterpret_cast<float4*>(&g_proj[((size_t)b * MPROJ + m) * HW + n0 + tx * 4]) = v;
    }
}

// ---------------- kernel 1b: reflect-pad channels 16..287 -----------------
__global__ void pad_kernel() {
    int idx = blockIdx.x * 256 + threadIdx.x;
    const int total = B_ * PC_ * PH * PW;
    if (idx >= total) return;
    int col = idx & 63;
    int rest = idx >> 6;
    int r = rest % PH;
    int cb = rest / PH;
    int c = cb % PC_;
    int b = cb / PC_;
    int oy = refl(r - 3, H_), ox = refl(col - 3, W_);
    g_pad[idx] = g_proj[((size_t)(b * MPROJ + 16 + c)) * HW + oy * W_ + ox];
}

// ---------------- kernel 2: attention weights + softmax (HMMA v2) ---------
// 8 pixels/block, 384 threads. Rows pt = k*8 + pix (tap-major).
__global__ __launch_bounds__(384, 3) void attn_kernel(
    const float* __restrict__ bn2g, const float* __restrict__ bn2b,
    const float* __restrict__ bn2m, const float* __restrict__ bn2v,
    const float* __restrict__ cb) {

    extern __shared__ __align__(16) char smem_raw[];
    __half* act0h = (__half*)(smem_raw + ATT_U0);     // [400][24] (phases 1-3)
    __half* slog2 = (__half*)(smem_raw + ATT_U0);     // [256][52] (phases 4-5, overlays act0h)
    __half* slog  = (__half*)(smem_raw + ATT_SLOG);   // [400][40]
    float*  sx2   = (float*)(smem_raw + ATT_SX2);     // [16][112]
    __half* scw1h = (__half*)(smem_raw + ATT_CW1H);
    __half* scw2h = (__half*)(smem_raw + ATT_CW2H);
    float*  sx1   = (float*)(smem_raw + ATT_SX1);
    float*  scb   = (float*)(smem_raw + ATT_SCB);
    float*  s2s   = (float*)(smem_raw + ATT_S2S);
    float*  t2s   = (float*)(smem_raw + ATT_T2S);
    float*  sinv  = (float*)(smem_raw + ATT_SINV);

    int t = threadIdx.x;
    int b = blockIdx.y;
    int p0 = blockIdx.x * 8;
    int h = p0 / W_, w0 = p0 % W_;

    // -------- staging --------
    if (t < 32) {
        reinterpret_cast<uint4*>(scw1h)[t] = reinterpret_cast<const uint4*>(g_cw1h)[t];
    } else if (t < 96) {
        reinterpret_cast<uint4*>(scw2h)[t - 32] = reinterpret_cast<const uint4*>(g_cw2h)[t - 32];
    } else if (t < 128) {
        scb[t - 96] = cb[t - 96];
    } else if (t < 144) {
        int c = t - 128;
        float ss = bn2g[c] * rsqrtf(bn2v[c] + 1e-5f);
        s2s[c] = ss; t2s[c] = bn2b[c] - ss * bn2m[c];
    } else if (t < 272) {
        int idx = t - 144;
        int c = idx >> 3, pix = idx & 7;
        sx1[pix * 16 + c] = g_proj[((size_t)b * MPROJ + c) * HW + p0 + pix];
    }
    const float* padb = g_pad + (size_t)b * PC_ * PH * PW;
    for (int i = t; i < 448; i += 384) {
        int c = i / 28, rem = i - c * 28, dy = rem >> 2, cg = rem & 3;
        float4 v = *reinterpret_cast<const float4*>(
            padb + ((size_t)c * PH + h + dy) * PW + w0 + cg * 4);
        *reinterpret_cast<float4*>(sx2 + c * 112 + dy * 16 + cg * 4) = v;
    }
    __syncthreads();

    // -------- phase1: act = relu(x1' - x2') -> fp16, rows pt = k*8+pix ----
    for (int pt = t; pt < 392; pt += 384) {
        int pix = pt & 7, k = pt >> 3;
        int dy = k / 7, dx = k - dy * 7;
        const float* x2p = sx2 + dy * 16 + dx + pix;
        const float* x1p = sx1 + pix * 16;
        __half2* dst = reinterpret_cast<__half2*>(act0h + pt * 24);
#pragma unroll
        for (int q = 0; q < 8; q++) {
            float a0 = fmaxf(x1p[2 * q]     - x2p[(2 * q) * 112],     0.0f);
            float a1 = fmaxf(x1p[2 * q + 1] - x2p[(2 * q + 1) * 112], 0.0f);
            dst[q] = __floats2half2_rn(a0, a1);
        }
    }
    __syncthreads();

    // -------- phase2+3: HMMA GEMM1 (16x16) -> BN2+ReLU -> GEMM2 (16x32) ---
    {
        int warp = t >> 5, lane = t & 31;
        int qp = lane & 3, rp = lane >> 2;
        int k0 = qp * 2;

        unsigned b1f[2][2], b2f[4][2];
#pragma unroll
        for (int j = 0; j < 2; j++) {
            int o = j * 8 + rp;
            b1f[j][0] = *reinterpret_cast<const unsigned*>(scw1h + o * 16 + k0);
            b1f[j][1] = *reinterpret_cast<const unsigned*>(scw1h + o * 16 + k0 + 8);
        }
#pragma unroll
        for (int j = 0; j < 4; j++) {
            int g = j * 8 + rp;
            b2f[j][0] = *reinterpret_cast<const unsigned*>(scw2h + g * 16 + k0);
            b2f[j][1] = *reinterpret_cast<const unsigned*>(scw2h + g * 16 + k0 + 8);
        }
        float s2v[4] = {s2s[k0], s2s[k0 + 1], s2s[k0 + 8], s2s[k0 + 9]};
        float t2v[4] = {t2s[k0], t2s[k0 + 1], t2s[k0 + 8], t2s[k0 + 9]};
        float cbv[4][2];
#pragma unroll
        for (int j = 0; j < 4; j++) {
            cbv[j][0] = scb[j * 8 + k0];
            cbv[j][1] = scb[j * 8 + k0 + 1];
        }

        uint32_t act_base = (uint32_t)__cvta_generic_to_shared(act0h);
        for (int tile = warp; tile < 25; tile += 12) {
            unsigned a1[4];
            uint32_t addr = act_base + (uint32_t)(tile * 16 + (lane & 15)) * 48u
                          + (uint32_t)(lane >> 4) * 16u;
            ldmatrix_x4(a1, addr);

            float z4[4] = {0.f, 0.f, 0.f, 0.f};
            float d0[4], d1[4];
            mma16816(d0, a1, b1f[0], z4);
            mma16816(d1, a1, b1f[1], z4);

            unsigned a2[4];
            {
                __half2 hv;
                hv = __floats2half2_rn(fmaxf(fmaf(s2v[0], d0[0], t2v[0]), 0.f),
                                       fmaxf(fmaf(s2v[1], d0[1], t2v[1]), 0.f));
                a2[0] = *reinterpret_cast<unsigned*>(&hv);
                hv = __floats2half2_rn(fmaxf(fmaf(s2v[0], d0[2], t2v[0]), 0.f),
                                       fmaxf(fmaf(s2v[1], d0[3], t2v[1]), 0.f));
                a2[1] = *reinterpret_cast<unsigned*>(&hv);
                hv = __floats2half2_rn(fmaxf(fmaf(s2v[2], d1[0], t2v[2]), 0.f),
                                       fmaxf(fmaf(s2v[3], d1[1], t2v[3]), 0.f));
                a2[2] = *reinterpret_cast<unsigned*>(&hv);
                hv = __floats2half2_rn(fmaxf(fmaf(s2v[2], d1[2], t2v[2]), 0.f),
                                       fmaxf(fmaf(s2v[3], d1[3], t2v[3]), 0.f));
                a2[3] = *reinterpret_cast<unsigned*>(&hv);
            }

            int r0 = tile * 16 + rp;
            bool hi_ok = (r0 + 8 < 392);   // false only for tile 24
#pragma unroll
            for (int j = 0; j < 4; j++) {
                float c2[4] = {cbv[j][0], cbv[j][1], cbv[j][0], cbv[j][1]};
                mma16816(c2, a2, b2f[j], c2);
                int g0 = j * 8 + k0;
                *reinterpret_cast<__half2*>(slog + r0 * 40 + g0) =
                    __floats2half2_rn(c2[0], c2[1]);
                if (hi_ok)
                    *reinterpret_cast<__half2*>(slog + (r0 + 8) * 40 + g0) =
                        __floats2half2_rn(c2[2], c2[3]);
            }
        }
    }
    __syncthreads();

    // -------- phase4: softmax; exp staged into slog2 (R7 layout) ----------
    // thread = (pix, g); slog reads conflict-free (lane g consecutive halves)
    if (t < 256) {
        int pix = t >> 5, g = t & 31;
        const __half* src = slog + pix * 40 + g;     // k-stride 320 halves
        float m = -1e30f;
#pragma unroll
        for (int k = 0; k < 49; k++) m = fmaxf(m, __half2float(src[k * 320]));
        __half* dst = slog2 + (pix * 32 + g) * 52;
        float s = 0.0f;
#pragma unroll
        for (int k = 0; k < 49; k++) {
            float e = __expf(__half2float(src[k * 320]) - m);
            s += e;
            dst[k] = __float2half(e);
        }
        dst[49] = __float2half(0.0f);
        dst[50] = __float2half(0.0f);
        dst[51] = __float2half(0.0f);
        sinv[t] = 1.0f / s;
    }
    __syncthreads();

    // -------- phase5: scale + coalesced fp16 g_w writes (R7 verbatim) -----
    {
        __half2* gw2 = reinterpret_cast<__half2*>(g_w);
        const __half2* sl2 = reinterpret_cast<const __half2*>(slog2);
        int r = t / 26, k2 = t - r * 26;
        for (int i = t; i < 6656; i += 384) {
            int pix = r >> 5, g = r & 31;
            float2 f = __half22float2(sl2[r * 26 + k2]);
            float inv = sinv[r];
            gw2[(((size_t)(b * WS_ + g)) * HW + p0 + pix) * 26 + k2] =
                __floats2half2_rn(f.x * inv, f.y * inv);
            r += 14; k2 += 20;
            if (k2 >= 26) { k2 -= 26; r++; }
        }
    }
}

// ---------------- kernel 3: aggregation -----------------------------------
__global__ __launch_bounds__(128) void agg_kernel() {
    __shared__ __align__(4) __half swh[64 * KP];
    __shared__ __align__(16) float sx3[8 * 14 * 24];

    int b = blockIdx.z, g = blockIdx.y, tile = blockIdx.x;
    int ty0 = (tile / 7) * 8, tx0 = (tile % 7) * 8;
    int t = threadIdx.x;

    const __half2* gw2 = reinterpret_cast<const __half2*>(g_w);
    size_t wbase = ((size_t)(b * WS_ + g)) * HW;
    for (int i = t; i < 1664; i += 128) {
        int run = i / 208, off = i - run * 208;
        reinterpret_cast<__half2*>(swh)[run * 208 + off] =
            gw2[(wbase + (ty0 + run) * W_ + tx0) * 26 + off];
    }
    const float* padb = g_pad + ((size_t)(b * PC_) + 16 + g * 8) * PH * PW;
    for (int i = t; i < 448; i += 128) {
        int c = i / 56, rem = i - c * 56, r = rem >> 2, cg = rem & 3;
        float4 v = *reinterpret_cast<const float4*>(
            padb + ((size_t)c * PH + ty0 + r) * PW + tx0 + cg * 4);
        *reinterpret_cast<float4*>(sx3 + (c * 14 + r) * 24 + cg * 4) = v;
    }
    __syncthreads();

    int pl = t & 63, sq = t >> 6;
    int pr = pl >> 3, pc = pl & 7;
    const __half2* wp = reinterpret_cast<const __half2*>(swh + pl * KP);
    const float* xb = sx3 + sq * 4 * 336 + pr * 24 + pc;

    float a0 = 0.f, a1 = 0.f, a2 = 0.f, a3 = 0.f;
#pragma unroll
    for (int k2 = 0; k2 < 25; k2++) {
        float2 wf = __half22float2(wp[k2]);
        {
            int k = 2 * k2;
            int xo = (k / 7) * 24 + (k % 7);
            a0 = fmaf(xb[xo],        wf.x, a0);
            a1 = fmaf(xb[336 + xo],  wf.x, a1);
            a2 = fmaf(xb[672 + xo],  wf.x, a2);
            a3 = fmaf(xb[1008 + xo], wf.x, a3);
        }
        if (2 * k2 + 1 < 49) {
            int k = 2 * k2 + 1;
            int xo = (k / 7) * 24 + (k % 7);
            a0 = fmaf(xb[xo],        wf.y, a0);
            a1 = fmaf(xb[336 + xo],  wf.y, a1);
            a2 = fmaf(xb[672 + xo],  wf.y, a2);
            a3 = fmaf(xb[1008 + xo], wf.y, a3);
        }
    }
    int p = (ty0 + pr) * W_ + tx0 + pc;
    float* dst = g_agg + ((size_t)b * OUT_ + g * 8 + sq * 4) * HW + p;
    dst[0] = a0; dst[HW] = a1; dst[2 * HW] = a2; dst[3 * HW] = a3;
}

// ---------------- kernel 4: position2 grouped conv ------------------------
__global__ __launch_bounds__(128) void pos2_kernel(const float* __restrict__ pos2w,
                                                   float* __restrict__ out) {
    __shared__ __align__(16) float sw[64 * KP];
    __shared__ __align__(16) float spw[8 * 60];
    __shared__ float sxv[8 * 64];

    int b = blockIdx.z, g = blockIdx.y, p0 = blockIdx.x * 64;
    int t = threadIdx.x;

    const __half2* gw2 = reinterpret_cast<const __half2*>(g_w);
    size_t base2 = (((size_t)(b * WS_ + g)) * HW + p0) * 26;
    for (int i = t; i < 1664; i += 128) {
        float2 f = __half22float2(gw2[base2 + i]);
        *reinterpret_cast<float2*>(sw + 2 * i) = f;
    }
    for (int i = t; i < 480; i += 128) {
        int o = i / 60, q = i - o * 60;
        spw[i] = (q < 57) ? pos2w[(g * 8 + o) * 57 + q] : 0.0f;
    }
    for (int i = t; i < 512; i += 128) {
        int s = i >> 6, pl = i & 63;
        sxv[i] = g_agg[((size_t)b * OUT_ + s * 32 + g) * HW + p0 + pl];
    }
    __syncthreads();

    int pl = t & 63, oh = t >> 6;
    float acc[4] = {0.f, 0.f, 0.f, 0.f};
#pragma unroll
    for (int s = 0; s < 8; s++) {
        float xv = sxv[s * 64 + pl];
#pragma unroll
        for (int j = 0; j < 4; j++)
            acc[j] = fmaf(xv, spw[(oh * 4 + j) * 60 + s], acc[j]);
    }
    const float4* w4 = reinterpret_cast<const float4*>(sw + pl * KP);
#pragma unroll
    for (int k4 = 0; k4 < 13; k4++) {
        float4 wv = w4[k4];
#pragma unroll
        for (int j = 0; j < 4; j++) {
            float4 pv = *reinterpret_cast<const float4*>(spw + (oh * 4 + j) * 60 + 8 + k4 * 4);
            acc[j] = fmaf(wv.x, pv.x, acc[j]);
            acc[j] = fmaf(wv.y, pv.y, acc[j]);
            acc[j] = fmaf(wv.z, pv.z, acc[j]);
            acc[j] = fmaf(wv.w, pv.w, acc[j]);
        }
    }
#pragma unroll
    for (int j = 0; j < 4; j++)
        out[((size_t)b * OUT_ + g * 8 + oh * 4 + j) * HW + p0 + pl] = acc[j];
}

// ---------------- launch ---------------------------------------------------
extern "C" void kernel_launch(void* const* d_in, const int* in_sizes, int n_in,
                              void* d_out, int out_size) {
    const float* x    = (const float*)d_in[0];
    const float* w1   = (const float*)d_in[1];
    const float* b1   = (const float*)d_in[2];
    const float* w2   = (const float*)d_in[3];
    const float* b2   = (const float*)d_in[4];
    const float* w3   = (const float*)d_in[5];
    const float* b3   = (const float*)d_in[6];
    const float* bn1g = (const float*)d_in[7];
    const float* bn1b = (const float*)d_in[8];
    const float* bn1m = (const float*)d_in[9];
    const float* bn1v = (const float*)d_in[10];
    const float* cw1  = (const float*)d_in[11];
    const float* bn2g = (const float*)d_in[12];
    const float* bn2b = (const float*)d_in[13];
    const float* bn2m = (const float*)d_in[14];
    const float* bn2v = (const float*)d_in[15];
    const float* cw2  = (const float*)d_in[16];
    const float* cb   = (const float*)d_in[17];
    const float* p2w  = (const float*)d_in[18];
    float* out = (float*)d_out;

    cudaFuncSetAttribute(attn_kernel, cudaFuncAttributeMaxDynamicSharedMemorySize, ATT_SMEM);

    pack_kernel<<<(MPROJ * CIN + 255) / 256, 256>>>(w1, b1, w2, b2, w3, b3,
                                                    bn1g, bn1b, bn1m, bn1v, cw1, cw2);

    dim3 gg(HW / BN, MPROJ / BM, B_);
    proj_gemm<<<gg, 256>>>(x);

    const int pad_total = B_ * PC_ * PH * PW;
    pad_kernel<<<(pad_total + 255) / 256, 256>>>();

    attn_kernel<<<dim3(HW / 8, B_), 384, ATT_SMEM>>>(bn2g, bn2b, bn2m, bn2v, cb);

    dim3 ga(49, WS_, B_);
    agg_kernel<<<ga, 128>>>();
    pos2_kernel<<<ga, 128>>>(p2w, out);
}

// round 12
// speedup vs baseline: 1.3688x; 1.1036x over previous
#include <cuda_runtime.h>
#include <cuda_fp16.h>
#include <cstdint>

// ---------------- problem constants ----------------
#define B_    4
#define CIN   256
#define H_    56
#define W_    56
#define HW    3136
#define OUT_  256
#define WS_   32
#define K2    49
#define KP    52
#define MPROJ 288
#define PC_   272
#define PH    62
#define PW    64

// attn dynamic smem layout (bytes) — R11 winner
#define ATT_U0     0
#define ATT_SLOG   26624
#define ATT_SX2    58624
#define ATT_CW1H   65792
#define ATT_CW2H   66304
#define ATT_SX1    67328
#define ATT_SCB    67840
#define ATT_S2S    67968
#define ATT_T2S    68032
#define ATT_SINV   68096
#define ATT_SMEM   69120

// ---------------- scratch (device globals) --------------------------------
__device__ float  g_bc[MPROJ];
__device__ float  g_s1[16], g_t1[16];
__device__ __align__(16) __half g_cw1h[256];   // [o][c] fp16
__device__ __align__(16) __half g_cw2h[512];   // [g][o] fp16
__device__ __align__(16) __half g_wch_b[MPROJ * CIN];   // W big  [m][k]
__device__ __align__(16) __half g_wch_s[MPROJ * CIN];   // W small
__device__ __align__(16) __half g_xtb[(size_t)B_ * HW * CIN];  // X^T big  [b][px][k]
__device__ __align__(16) __half g_xts[(size_t)B_ * HW * CIN];  // X^T small
__device__ float  g_proj[B_ * MPROJ * HW];
__device__ float  g_pad[(size_t)B_ * PC_ * PH * PW];
__device__ __half g_w[(size_t)B_ * WS_ * HW * KP];
__device__ float  g_agg[B_ * OUT_ * HW];

__device__ __forceinline__ int refl(int i, int n) {
    if (i < 0) i = -i;
    if (i >= n) i = 2 * n - 2 - i;
    return i;
}

__device__ __forceinline__ void mma16816(float (&d)[4], const unsigned (&a)[4],
                                         const unsigned (&b)[2], const float (&c)[4]) {
    asm volatile(
        "mma.sync.aligned.m16n8k16.row.col.f32.f16.f16.f32 "
        "{%0,%1,%2,%3}, {%4,%5,%6,%7}, {%8,%9}, {%10,%11,%12,%13};\n"
        : "=f"(d[0]), "=f"(d[1]), "=f"(d[2]), "=f"(d[3])
        : "r"(a[0]), "r"(a[1]), "r"(a[2]), "r"(a[3]),
          "r"(b[0]), "r"(b[1]),
          "f"(c[0]), "f"(c[1]), "f"(c[2]), "f"(c[3]));
}

__device__ __forceinline__ void ldmatrix_x4(unsigned (&r)[4], uint32_t addr) {
    asm volatile("ldmatrix.sync.aligned.m8n8.x4.shared.b16 {%0,%1,%2,%3}, [%4];\n"
                 : "=r"(r[0]), "=r"(r[1]), "=r"(r[2]), "=r"(r[3]) : "r"(addr));
}

// ---------------- kernel 0: pack weights + bn1 fold + fp16 splits ---------
__global__ void pack_kernel(const float* __restrict__ w1, const float* __restrict__ b1,
                            const float* __restrict__ w2, const float* __restrict__ b2,
                            const float* __restrict__ w3, const float* __restrict__ b3,
                            const float* __restrict__ bn1g, const float* __restrict__ bn1b,
                            const float* __restrict__ bn1m, const float* __restrict__ bn1v,
                            const float* __restrict__ cw1, const float* __restrict__ cw2) {
    int i = blockIdx.x * blockDim.x + threadIdx.x;
    if (i < MPROJ * CIN) {
        int r = i / CIN, c = i % CIN;
        float v;
        if (r < 16)      v = w1[r * CIN + c];
        else if (r < 32) v = w2[(r - 16) * CIN + c];
        else             v = w3[(r - 32) * CIN + c];
        __half hb = __float2half(v);
        g_wch_b[i] = hb;
        g_wch_s[i] = __float2half(v - __half2float(hb));
    }
    if (i < MPROJ) {
        g_bc[i] = (i < 16) ? b1[i] : ((i < 32) ? b2[i - 16] : b3[i - 32]);
    }
    if (i < 16) {
        float s = bn1g[i] * rsqrtf(bn1v[i] + 1e-5f);
        g_s1[i] = s;
        g_t1[i] = bn1b[i] - s * bn1m[i];
    }
    if (i < 256) g_cw1h[i] = __float2half(cw1[i]);
    if (i < 512) g_cw2h[i] = __float2half(cw2[i]);
}

// ---------------- kernel 0b: transpose + fp16-split X ---------------------
// x [b][k][px] fp32 -> g_xtb/g_xts [b][px][k] fp16
__global__ __launch_bounds__(256) void prep_x(const float* __restrict__ x) {
    __shared__ float tile[32][33];
    int p0 = blockIdx.x * 32, k0 = blockIdx.y * 32, b = blockIdx.z;
    int t = threadIdx.x;
    for (int i = t; i < 1024; i += 256) {
        int kk = i >> 5, pp = i & 31;
        tile[kk][pp] = x[((size_t)(b * CIN + k0 + kk)) * HW + p0 + pp];
    }
    __syncthreads();
    for (int i = t; i < 1024; i += 256) {
        int pp = i >> 5, kk = i & 31;
        float v = tile[kk][pp];
        __half hb = __float2half(v);
        size_t o = ((size_t)(b * HW + p0 + pp)) * CIN + k0 + kk;
        g_xtb[o] = hb;
        g_xts[o] = __float2half(v - __half2float(hb));
    }
}

// ---------------- kernel 1: projection GEMM via 3-term fp16 HMMA ----------
// block = 64 px x 96 ch; 8 warps = 4 px m-tiles x 2 ch halves (6 n8-tiles each)
__global__ __launch_bounds__(256) void proj_gemm() {
    __shared__ __align__(16) __half Xb[64 * 72], Xs[64 * 72];   // [px][72] (64 used)
    __shared__ __align__(16) __half Wb[96 * 72], Ws[96 * 72];   // [ch][72] (64 used)

    int b  = blockIdx.z;
    int p0 = blockIdx.x * 64;
    int ch0 = blockIdx.y * 96;
    int t  = threadIdx.x;
    int warp = t >> 5, lane = t & 31;
    int mt = warp >> 1, nh = warp & 1;
    int qp = lane & 3, rp = lane >> 2;

    float acc[6][4];
#pragma unroll
    for (int j = 0; j < 6; j++)
#pragma unroll
        for (int c = 0; c < 4; c++) acc[j][c] = 0.0f;

    uint32_t xb_base = (uint32_t)__cvta_generic_to_shared(Xb);
    uint32_t xs_base = (uint32_t)__cvta_generic_to_shared(Xs);
    uint32_t a_off = (uint32_t)(mt * 16 + (lane & 15)) * 144u + (uint32_t)(lane >> 4) * 16u;

    const uint4* gxb4 = reinterpret_cast<const uint4*>(g_xtb);
    const uint4* gxs4 = reinterpret_cast<const uint4*>(g_xts);
    const uint4* gwb4 = reinterpret_cast<const uint4*>(g_wch_b);
    const uint4* gws4 = reinterpret_cast<const uint4*>(g_wch_s);

    for (int k0 = 0; k0 < CIN; k0 += 64) {
        int kq = k0 >> 3;   // uint4 offset within a 256-half row (32 uint4/row)
        for (int i = t; i < 512; i += 256) {
            int r = i >> 3, c = i & 7;
            size_t src = (size_t)(b * HW + p0 + r) * 32 + kq + c;
            reinterpret_cast<uint4*>(Xb)[r * 9 + c] = gxb4[src];
            reinterpret_cast<uint4*>(Xs)[r * 9 + c] = gxs4[src];
        }
        for (int i = t; i < 768; i += 256) {
            int r = i >> 3, c = i & 7;
            size_t src = (size_t)(ch0 + r) * 32 + kq + c;
            reinterpret_cast<uint4*>(Wb)[r * 9 + c] = gwb4[src];
            reinterpret_cast<uint4*>(Ws)[r * 9 + c] = gws4[src];
        }
        __syncthreads();

#pragma unroll
        for (int kk = 0; kk < 4; kk++) {
            unsigned axb[4], axs[4];
            ldmatrix_x4(axb, xb_base + a_off + (uint32_t)kk * 32u);
            ldmatrix_x4(axs, xs_base + a_off + (uint32_t)kk * 32u);
#pragma unroll
            for (int j = 0; j < 6; j++) {
                int ch = (nh * 6 + j) * 8 + rp;
                const __half* wbp = Wb + ch * 72 + kk * 16 + 2 * qp;
                const __half* wsp = Ws + ch * 72 + kk * 16 + 2 * qp;
                unsigned bb[2] = {*reinterpret_cast<const unsigned*>(wbp),
                                  *reinterpret_cast<const unsigned*>(wbp + 8)};
                unsigned bs[2] = {*reinterpret_cast<const unsigned*>(wsp),
                                  *reinterpret_cast<const unsigned*>(wsp + 8)};
                mma16816(acc[j], axb, bb, acc[j]);
                mma16816(acc[j], axs, bb, acc[j]);
                mma16816(acc[j], axb, bs, acc[j]);
            }
        }
        __syncthreads();
    }

    // epilogue: bias + BN1 fold; lane holds (px=pxl/pxl+8, ch=chg/chg+1)
    int pxl = p0 + mt * 16 + rp;
#pragma unroll
    for (int j = 0; j < 6; j++) {
        int chg = ch0 + (nh * 6 + j) * 8 + 2 * qp;
        float b0 = g_bc[chg], b1 = g_bc[chg + 1];
        float v0 = acc[j][0] + b0, v1 = acc[j][1] + b1;
        float v2 = acc[j][2] + b0, v3 = acc[j][3] + b1;
        if (chg < 16)      { float s = g_s1[chg], tt = g_t1[chg];
                             v0 = fmaf(s, v0, tt); v2 = fmaf(s, v2, tt); }
        else if (chg < 32) { float s = g_s1[chg - 16]; v0 *= s; v2 *= s; }
        int ch1 = chg + 1;
        if (ch1 < 16)      { float s = g_s1[ch1], tt = g_t1[ch1];
                             v1 = fmaf(s, v1, tt); v3 = fmaf(s, v3, tt); }
        else if (ch1 < 32) { float s = g_s1[ch1 - 16]; v1 *= s; v3 *= s; }
        size_t r0 = (size_t)(b * MPROJ + chg) * HW;
        size_t r1 = (size_t)(b * MPROJ + ch1) * HW;
        g_proj[r0 + pxl]     = v0;
        g_proj[r1 + pxl]     = v1;
        g_proj[r0 + pxl + 8] = v2;
        g_proj[r1 + pxl + 8] = v3;
    }
}

// ---------------- kernel 1b: reflect-pad channels 16..287 -----------------
__global__ void pad_kernel() {
    int idx = blockIdx.x * 256 + threadIdx.x;
    const int total = B_ * PC_ * PH * PW;
    if (idx >= total) return;
    int col = idx & 63;
    int rest = idx >> 6;
    int r = rest % PH;
    int cb = rest / PH;
    int c = cb % PC_;
    int b = cb / PC_;
    int oy = refl(r - 3, H_), ox = refl(col - 3, W_);
    g_pad[idx] = g_proj[((size_t)(b * MPROJ + 16 + c)) * HW + oy * W_ + ox];
}

// ---------------- kernel 2: attention weights + softmax (R11 HMMA) --------
__global__ __launch_bounds__(384, 3) void attn_kernel(
    const float* __restrict__ bn2g, const float* __restrict__ bn2b,
    const float* __restrict__ bn2m, const float* __restrict__ bn2v,
    const float* __restrict__ cb) {

    extern __shared__ __align__(16) char smem_raw[];
    __half* act0h = (__half*)(smem_raw + ATT_U0);
    __half* slog2 = (__half*)(smem_raw + ATT_U0);
    __half* slog  = (__half*)(smem_raw + ATT_SLOG);
    float*  sx2   = (float*)(smem_raw + ATT_SX2);
    __half* scw1h = (__half*)(smem_raw + ATT_CW1H);
    __half* scw2h = (__half*)(smem_raw + ATT_CW2H);
    float*  sx1   = (float*)(smem_raw + ATT_SX1);
    float*  scb   = (float*)(smem_raw + ATT_SCB);
    float*  s2s   = (float*)(smem_raw + ATT_S2S);
    float*  t2s   = (float*)(smem_raw + ATT_T2S);
    float*  sinv  = (float*)(smem_raw + ATT_SINV);

    int t = threadIdx.x;
    int b = blockIdx.y;
    int p0 = blockIdx.x * 8;
    int h = p0 / W_, w0 = p0 % W_;

    if (t < 32) {
        reinterpret_cast<uint4*>(scw1h)[t] = reinterpret_cast<const uint4*>(g_cw1h)[t];
    } else if (t < 96) {
        reinterpret_cast<uint4*>(scw2h)[t - 32] = reinterpret_cast<const uint4*>(g_cw2h)[t - 32];
    } else if (t < 128) {
        scb[t - 96] = cb[t - 96];
    } else if (t < 144) {
        int c = t - 128;
        float ss = bn2g[c] * rsqrtf(bn2v[c] + 1e-5f);
        s2s[c] = ss; t2s[c] = bn2b[c] - ss * bn2m[c];
    } else if (t < 272) {
        int idx = t - 144;
        int c = idx >> 3, pix = idx & 7;
        sx1[pix * 16 + c] = g_proj[((size_t)b * MPROJ + c) * HW + p0 + pix];
    }
    const float* padb = g_pad + (size_t)b * PC_ * PH * PW;
    for (int i = t; i < 448; i += 384) {
        int c = i / 28, rem = i - c * 28, dy = rem >> 2, cg = rem & 3;
        float4 v = *reinterpret_cast<const float4*>(
            padb + ((size_t)c * PH + h + dy) * PW + w0 + cg * 4);
        *reinterpret_cast<float4*>(sx2 + c * 112 + dy * 16 + cg * 4) = v;
    }
    __syncthreads();

    for (int pt = t; pt < 392; pt += 384) {
        int pix = pt & 7, k = pt >> 3;
        int dy = k / 7, dx = k - dy * 7;
        const float* x2p = sx2 + dy * 16 + dx + pix;
        const float* x1p = sx1 + pix * 16;
        __half2* dst = reinterpret_cast<__half2*>(act0h + pt * 24);
#pragma unroll
        for (int q = 0; q < 8; q++) {
            float a0 = fmaxf(x1p[2 * q]     - x2p[(2 * q) * 112],     0.0f);
            float a1 = fmaxf(x1p[2 * q + 1] - x2p[(2 * q + 1) * 112], 0.0f);
            dst[q] = __floats2half2_rn(a0, a1);
        }
    }
    __syncthreads();

    {
        int warp = t >> 5, lane = t & 31;
        int qp = lane & 3, rp = lane >> 2;
        int k0 = qp * 2;

        unsigned b1f[2][2], b2f[4][2];
#pragma unroll
        for (int j = 0; j < 2; j++) {
            int o = j * 8 + rp;
            b1f[j][0] = *reinterpret_cast<const unsigned*>(scw1h + o * 16 + k0);
            b1f[j][1] = *reinterpret_cast<const unsigned*>(scw1h + o * 16 + k0 + 8);
        }
#pragma unroll
        for (int j = 0; j < 4; j++) {
            int g = j * 8 + rp;
            b2f[j][0] = *reinterpret_cast<const unsigned*>(scw2h + g * 16 + k0);
            b2f[j][1] = *reinterpret_cast<const unsigned*>(scw2h + g * 16 + k0 + 8);
        }
        float s2v[4] = {s2s[k0], s2s[k0 + 1], s2s[k0 + 8], s2s[k0 + 9]};
        float t2v[4] = {t2s[k0], t2s[k0 + 1], t2s[k0 + 8], t2s[k0 + 9]};
        float cbv[4][2];
#pragma unroll
        for (int j = 0; j < 4; j++) {
            cbv[j][0] = scb[j * 8 + k0];
            cbv[j][1] = scb[j * 8 + k0 + 1];
        }

        uint32_t act_base = (uint32_t)__cvta_generic_to_shared(act0h);
        for (int tile = warp; tile < 25; tile += 12) {
            unsigned a1[4];
            uint32_t addr = act_base + (uint32_t)(tile * 16 + (lane & 15)) * 48u
                          + (uint32_t)(lane >> 4) * 16u;
            ldmatrix_x4(a1, addr);

            float z4[4] = {0.f, 0.f, 0.f, 0.f};
            float d0[4], d1[4];
            mma16816(d0, a1, b1f[0], z4);
            mma16816(d1, a1, b1f[1], z4);

            unsigned a2[4];
            {
                __half2 hv;
                hv = __floats2half2_rn(fmaxf(fmaf(s2v[0], d0[0], t2v[0]), 0.f),
                                       fmaxf(fmaf(s2v[1], d0[1], t2v[1]), 0.f));
                a2[0] = *reinterpret_cast<unsigned*>(&hv);
                hv = __floats2half2_rn(fmaxf(fmaf(s2v[0], d0[2], t2v[0]), 0.f),
                                       fmaxf(fmaf(s2v[1], d0[3], t2v[1]), 0.f));
                a2[1] = *reinterpret_cast<unsigned*>(&hv);
                hv = __floats2half2_rn(fmaxf(fmaf(s2v[2], d1[0], t2v[2]), 0.f),
                                       fmaxf(fmaf(s2v[3], d1[1], t2v[3]), 0.f));
                a2[2] = *reinterpret_cast<unsigned*>(&hv);
                hv = __floats2half2_rn(fmaxf(fmaf(s2v[2], d1[2], t2v[2]), 0.f),
                                       fmaxf(fmaf(s2v[3], d1[3], t2v[3]), 0.f));
                a2[3] = *reinterpret_cast<unsigned*>(&hv);
            }

            int r0 = tile * 16 + rp;
            bool hi_ok = (r0 + 8 < 392);
#pragma unroll
            for (int j = 0; j < 4; j++) {
                float c2[4] = {cbv[j][0], cbv[j][1], cbv[j][0], cbv[j][1]};
                mma16816(c2, a2, b2f[j], c2);
                int g0 = j * 8 + k0;
                *reinterpret_cast<__half2*>(slog + r0 * 40 + g0) =
                    __floats2half2_rn(c2[0], c2[1]);
                if (hi_ok)
                    *reinterpret_cast<__half2*>(slog + (r0 + 8) * 40 + g0) =
                        __floats2half2_rn(c2[2], c2[3]);
            }
        }
    }
    __syncthreads();

    if (t < 256) {
        int pix = t >> 5, g = t & 31;
        const __half* src = slog + pix * 40 + g;
        float m = -1e30f;
#pragma unroll
        for (int k = 0; k < 49; k++) m = fmaxf(m, __half2float(src[k * 320]));
        __half* dst = slog2 + (pix * 32 + g) * 52;
        float s = 0.0f;
#pragma unroll
        for (int k = 0; k < 49; k++) {
            float e = __expf(__half2float(src[k * 320]) - m);
            s += e;
            dst[k] = __float2half(e);
        }
        dst[49] = __float2half(0.0f);
        dst[50] = __float2half(0.0f);
        dst[51] = __float2half(0.0f);
        sinv[t] = 1.0f / s;
    }
    __syncthreads();

    {
        __half2* gw2 = reinterpret_cast<__half2*>(g_w);
        const __half2* sl2 = reinterpret_cast<const __half2*>(slog2);
        int r = t / 26, k2 = t - r * 26;
        for (int i = t; i < 6656; i += 384) {
            int pix = r >> 5, g = r & 31;
            float2 f = __half22float2(sl2[r * 26 + k2]);
            float inv = sinv[r];
            gw2[(((size_t)(b * WS_ + g)) * HW + p0 + pix) * 26 + k2] =
                __floats2half2_rn(f.x * inv, f.y * inv);
            r += 14; k2 += 20;
            if (k2 >= 26) { k2 -= 26; r++; }
        }
    }
}

// ---------------- kernel 3: aggregation -----------------------------------
__global__ __launch_bounds__(128) void agg_kernel() {
    __shared__ __align__(4) __half swh[64 * KP];
    __shared__ __align__(16) float sx3[8 * 14 * 24];

    int b = blockIdx.z, g = blockIdx.y, tile = blockIdx.x;
    int ty0 = (tile / 7) * 8, tx0 = (tile % 7) * 8;
    int t = threadIdx.x;

    const __half2* gw2 = reinterpret_cast<const __half2*>(g_w);
    size_t wbase = ((size_t)(b * WS_ + g)) * HW;
    for (int i = t; i < 1664; i += 128) {
        int run = i / 208, off = i - run * 208;
        reinterpret_cast<__half2*>(swh)[run * 208 + off] =
            gw2[(wbase + (ty0 + run) * W_ + tx0) * 26 + off];
    }
    const float* padb = g_pad + ((size_t)(b * PC_) + 16 + g * 8) * PH * PW;
    for (int i = t; i < 448; i += 128) {
        int c = i / 56, rem = i - c * 56, r = rem >> 2, cg = rem & 3;
        float4 v = *reinterpret_cast<const float4*>(
            padb + ((size_t)c * PH + ty0 + r) * PW + tx0 + cg * 4);
        *reinterpret_cast<float4*>(sx3 + (c * 14 + r) * 24 + cg * 4) = v;
    }
    __syncthreads();

    int pl = t & 63, sq = t >> 6;
    int pr = pl >> 3, pc = pl & 7;
    const __half2* wp = reinterpret_cast<const __half2*>(swh + pl * KP);
    const float* xb = sx3 + sq * 4 * 336 + pr * 24 + pc;

    float a0 = 0.f, a1 = 0.f, a2 = 0.f, a3 = 0.f;
#pragma unroll
    for (int k2 = 0; k2 < 25; k2++) {
        float2 wf = __half22float2(wp[k2]);
        {
            int k = 2 * k2;
            int xo = (k / 7) * 24 + (k % 7);
            a0 = fmaf(xb[xo],        wf.x, a0);
            a1 = fmaf(xb[336 + xo],  wf.x, a1);
            a2 = fmaf(xb[672 + xo],  wf.x, a2);
            a3 = fmaf(xb[1008 + xo], wf.x, a3);
        }
        if (2 * k2 + 1 < 49) {
            int k = 2 * k2 + 1;
            int xo = (k / 7) * 24 + (k % 7);
            a0 = fmaf(xb[xo],        wf.y, a0);
            a1 = fmaf(xb[336 + xo],  wf.y, a1);
            a2 = fmaf(xb[672 + xo],  wf.y, a2);
            a3 = fmaf(xb[1008 + xo], wf.y, a3);
        }
    }
    int p = (ty0 + pr) * W_ + tx0 + pc;
    float* dst = g_agg + ((size_t)b * OUT_ + g * 8 + sq * 4) * HW + p;
    dst[0] = a0; dst[HW] = a1; dst[2 * HW] = a2; dst[3 * HW] = a3;
}

// ---------------- kernel 4: position2 grouped conv ------------------------
__global__ __launch_bounds__(128) void pos2_kernel(const float* __restrict__ pos2w,
                                                   float* __restrict__ out) {
    __shared__ __align__(16) float sw[64 * KP];
    __shared__ __align__(16) float spw[8 * 60];
    __shared__ float sxv[8 * 64];

    int b = blockIdx.z, g = blockIdx.y, p0 = blockIdx.x * 64;
    int t = threadIdx.x;

    const __half2* gw2 = reinterpret_cast<const __half2*>(g_w);
    size_t base2 = (((size_t)(b * WS_ + g)) * HW + p0) * 26;
    for (int i = t; i < 1664; i += 128) {
        float2 f = __half22float2(gw2[base2 + i]);
        *reinterpret_cast<float2*>(sw + 2 * i) = f;
    }
    for (int i = t; i < 480; i += 128) {
        int o = i / 60, q = i - o * 60;
        spw[i] = (q < 57) ? pos2w[(g * 8 + o) * 57 + q] : 0.0f;
    }
    for (int i = t; i < 512; i += 128) {
        int s = i >> 6, pl = i & 63;
        sxv[i] = g_agg[((size_t)b * OUT_ + s * 32 + g) * HW + p0 + pl];
    }
    __syncthreads();

    int pl = t & 63, oh = t >> 6;
    float acc[4] = {0.f, 0.f, 0.f, 0.f};
#pragma unroll
    for (int s = 0; s < 8; s++) {
        float xv = sxv[s * 64 + pl];
#pragma unroll
        for (int j = 0; j < 4; j++)
            acc[j] = fmaf(xv, spw[(oh * 4 + j) * 60 + s], acc[j]);
    }
    const float4* w4 = reinterpret_cast<const float4*>(sw + pl * KP);
#pragma unroll
    for (int k4 = 0; k4 < 13; k4++) {
        float4 wv = w4[k4];
#pragma unroll
        for (int j = 0; j < 4; j++) {
            float4 pv = *reinterpret_cast<const float4*>(spw + (oh * 4 + j) * 60 + 8 + k4 * 4);
            acc[j] = fmaf(wv.x, pv.x, acc[j]);
            acc[j] = fmaf(wv.y, pv.y, acc[j]);
            acc[j] = fmaf(wv.z, pv.z, acc[j]);
            acc[j] = fmaf(wv.w, pv.w, acc[j]);
        }
    }
#pragma unroll
    for (int j = 0; j < 4; j++)
        out[((size_t)b * OUT_ + g * 8 + oh * 4 + j) * HW + p0 + pl] = acc[j];
}

// ---------------- launch ---------------------------------------------------
extern "C" void kernel_launch(void* const* d_in, const int* in_sizes, int n_in,
                              void* d_out, int out_size) {
    const float* x    = (const float*)d_in[0];
    const float* w1   = (const float*)d_in[1];
    const float* b1   = (const float*)d_in[2];
    const float* w2   = (const float*)d_in[3];
    const float* b2   = (const float*)d_in[4];
    const float* w3   = (const float*)d_in[5];
    const float* b3   = (const float*)d_in[6];
    const float* bn1g = (const float*)d_in[7];
    const float* bn1b = (const float*)d_in[8];
    const float* bn1m = (const float*)d_in[9];
    const float* bn1v = (const float*)d_in[10];
    const float* cw1  = (const float*)d_in[11];
    const float* bn2g = (const float*)d_in[12];
    const float* bn2b = (const float*)d_in[13];
    const float* bn2m = (const float*)d_in[14];
    const float* bn2v = (const float*)d_in[15];
    const float* cw2  = (const float*)d_in[16];
    const float* cb   = (const float*)d_in[17];
    const float* p2w  = (const float*)d_in[18];
    float* out = (float*)d_out;

    cudaFuncSetAttribute(attn_kernel, cudaFuncAttributeMaxDynamicSharedMemorySize, ATT_SMEM);

    pack_kernel<<<(MPROJ * CIN + 255) / 256, 256>>>(w1, b1, w2, b2, w3, b3,
                                                    bn1g, bn1b, bn1m, bn1v, cw1, cw2);

    prep_x<<<dim3(HW / 32, CIN / 32, B_), 256>>>(x);

    proj_gemm<<<dim3(HW / 64, MPROJ / 96, B_), 256>>>();

    const int pad_total = B_ * PC_ * PH * PW;
    pad_kernel<<<(pad_total + 255) / 256, 256>>>();

    attn_kernel<<<dim3(HW / 8, B_), 384, ATT_SMEM>>>(bn2g, bn2b, bn2m, bn2v, cb);

    dim3 ga(49, WS_, B_);
    agg_kernel<<<ga, 128>>>();
    pos2_kernel<<<ga, 128>>>(p2w, out);
}